// round 13
// baseline (speedup 1.0000x reference)
#include <cuda_runtime.h>
#include <cuda_bf16.h>
#include <mma.h>
#include <math.h>
#include <cstdint>

using namespace nvcuda;

#define BB 2
#define TT 1024
#define DD 1024
#define HH 16
#define CH 64
#define BHN (BB*HH)
#define NCH 16

// ---------------- device scratch ----------------
__device__ __align__(128) float g_cum [BHN*TT];
__device__ __align__(128) float g_gate[BHN*TT*CH];

// bf16 hi/lo activations (written directly by proj_kernel)
__device__ __align__(128) __nv_bfloat16 g_Xh[BHN*TT*CH];
__device__ __align__(128) __nv_bfloat16 g_Xl[BHN*TT*CH];
__device__ __align__(128) __nv_bfloat16 g_Bh[BHN*TT*CH];
__device__ __align__(128) __nv_bfloat16 g_Bl[BHN*TT*CH];
__device__ __align__(128) __nv_bfloat16 g_Chh[BHN*TT*CH];
__device__ __align__(128) __nv_bfloat16 g_Cll[BHN*TT*CH];

// chunked-scan intermediates
__device__ __align__(128) float         g_P  [BHN*NCH*64*64];
__device__ __align__(128) __nv_bfloat16 g_Sth[BHN*NCH*64*64];
__device__ __align__(128) __nv_bfloat16 g_Stl[BHN*NCH*64*64];

// output GEMM operands
__device__ __align__(128) __nv_bfloat16 g_YgH[BB*TT*DD];
__device__ __align__(128) __nv_bfloat16 g_YgL[BB*TT*DD];
__device__ __align__(128) __nv_bfloat16 g_WH [DD*DD];
__device__ __align__(128) __nv_bfloat16 g_WL [DD*DD];

// ---------------- helpers ----------------
__device__ __forceinline__ uint32_t smem_u32(const void* p) {
    uint32_t a;
    asm("{ .reg .u64 t; cvta.to.shared.u64 t, %1; cvt.u32.u64 %0, t; }" : "=r"(a) : "l"(p));
    return a;
}
__device__ __forceinline__ void cp16(uint32_t dst, const void* src) {
    asm volatile("cp.async.cg.shared.global [%0], [%1], 16;" :: "r"(dst), "l"(src) : "memory");
}
#define CP_COMMIT() asm volatile("cp.async.commit_group;" ::: "memory")
#define CP_WAIT(n)  asm volatile("cp.async.wait_group %0;" :: "n"(n) : "memory")

// =================================================================================
// Kernel 1: fused per-head projections (fp32 FFMA). 256 outputs = 4 o-tiles.
// =================================================================================
__global__ __launch_bounds__(128) void proj_kernel(
    const float* __restrict__ inp,
    const float* __restrict__ W_XBC,  const float* __restrict__ b_XBC,
    const float* __restrict__ W_gate, const float* __restrict__ b_gate)
{
    __shared__ float As[64*68];
    __shared__ float Ws[64*68];

    const int h     = blockIdx.z;
    const int mbase = blockIdx.x * 64;
    const int obase = blockIdx.y * 64;
    const int tid   = threadIdx.x;

    for (int l4 = tid; l4 < 64*16; l4 += 128) {
        int r = l4 >> 4, c4 = l4 & 15;
        float4 v = *(const float4*)&inp[(size_t)(mbase + r) * DD + h*CH + c4*4];
        *(float4*)&As[r*68 + c4*4] = v;
    }
    for (int l4 = tid; l4 < 64*16; l4 += 128) {
        int r = l4 >> 4, c4 = l4 & 15;
        int o = obase + r;
        float4 v;
        if (o < 192) v = *(const float4*)&W_XBC[((size_t)(h*192) + o)*CH + c4*4];
        else         v = *(const float4*)&W_gate[((size_t)(h*CH) + (o-192))*CH + c4*4];
        *(float4*)&Ws[r*68 + c4*4] = v;
    }
    __syncthreads();

    const int ty = tid >> 4, tx = tid & 15;
    float acc[8][4];
#pragma unroll
    for (int i = 0; i < 8; ++i)
#pragma unroll
        for (int j = 0; j < 4; ++j) acc[i][j] = 0.f;

#pragma unroll
    for (int k4 = 0; k4 < 16; ++k4) {
        float4 a[8], b[4];
#pragma unroll
        for (int i = 0; i < 8; ++i) a[i] = *(float4*)&As[(ty + 8*i)*68 + k4*4];
#pragma unroll
        for (int j = 0; j < 4; ++j) b[j] = *(float4*)&Ws[(tx + 16*j)*68 + k4*4];
#pragma unroll
        for (int i = 0; i < 8; ++i)
#pragma unroll
            for (int j = 0; j < 4; ++j) {
                acc[i][j] += a[i].x*b[j].x;
                acc[i][j] += a[i].y*b[j].y;
                acc[i][j] += a[i].z*b[j].z;
                acc[i][j] += a[i].w*b[j].w;
            }
    }

#pragma unroll
    for (int i = 0; i < 8; ++i) {
#pragma unroll
        for (int j = 0; j < 4; ++j) {
            int o  = obase + tx + 16*j;
            int m  = mbase + ty + 8*i;
            int b_ = m >> 10;
            int t  = m & (TT-1);
            int bh = b_*HH + h;
            float v = acc[i][j];
            if (o < 192) {
                float z = v + b_XBC[h*192 + o];
                float s = z / (1.f + __expf(-z));
                __nv_bfloat16 hi = __float2bfloat16_rn(s);
                __nv_bfloat16 lo = __float2bfloat16_rn(s - __bfloat162float(hi));
                size_t idx;
                if (o < 64)       { idx = ((size_t)bh*TT + t)*CH + o;       g_Xh[idx]=hi; g_Xl[idx]=lo; }
                else if (o < 128) { idx = ((size_t)bh*TT + t)*CH + (o-64);  g_Bh[idx]=hi; g_Bl[idx]=lo; }
                else              { idx = ((size_t)bh*TT + t)*CH + (o-128); g_Chh[idx]=hi; g_Cll[idx]=lo; }
            } else {
                g_gate[((size_t)bh*TT + t)*CH + (o-192)] = v + b_gate[h*CH + (o-192)];
            }
        }
    }
}

// =================================================================================
// Kernel 2: merged (a) W_out hi/lo cvt (blocks 0..1023) and
//           (b) logA GEMV + cumsum (blocks 1024..1055).
// =================================================================================
__global__ __launch_bounds__(256) void scan_cvt_kernel(
    const float* __restrict__ inp,
    const float* __restrict__ W_logA, const float* __restrict__ b_logA,
    const float* __restrict__ W_out)
{
    const int tid = threadIdx.x;

    if (blockIdx.x < 1024) {
        const int i = blockIdx.x * 256 + tid;
        float4 v = ((const float4*)W_out)[i];
        float x[4] = {v.x, v.y, v.z, v.w};
        __nv_bfloat16 h[4], l[4];
#pragma unroll
        for (int k = 0; k < 4; ++k) {
            h[k] = __float2bfloat16_rn(x[k]);
            l[k] = __float2bfloat16_rn(x[k] - __bfloat162float(h[k]));
        }
        ((__nv_bfloat162*)g_WH)[i*2+0] = __halves2bfloat162(h[0], h[1]);
        ((__nv_bfloat162*)g_WH)[i*2+1] = __halves2bfloat162(h[2], h[3]);
        ((__nv_bfloat162*)g_WL)[i*2+0] = __halves2bfloat162(l[0], l[1]);
        ((__nv_bfloat162*)g_WL)[i*2+1] = __halves2bfloat162(l[2], l[3]);
        return;
    }

    __shared__ float s_tot[256];
    __shared__ float w[64];
    const int bh  = blockIdx.x - 1024;
    const int b_  = bh >> 4, h = bh & 15;

    if (tid < 64) w[tid] = W_logA[h*CH + tid];
    __syncthreads();
    const float bA = b_logA[h];

    float v[4];
#pragma unroll
    for (int j = 0; j < 4; ++j) {
        const int t = tid*4 + j;
        const float4* row = (const float4*)&inp[((size_t)b_*TT + t)*DD + h*CH];
        float dot = 0.f;
#pragma unroll
        for (int c4 = 0; c4 < 16; ++c4) {
            float4 x = row[c4];
            dot += x.x*w[c4*4+0] + x.y*w[c4*4+1] + x.z*w[c4*4+2] + x.w*w[c4*4+3];
        }
        v[j] = dot + bA;
    }

    float r0 = v[0], r1 = r0+v[1], r2 = r1+v[2], r3 = r2+v[3];
    float total = r3;
    s_tot[tid] = r3;

    for (int off = 1; off < 256; off <<= 1) {
        __syncthreads();
        float add = (tid >= off) ? s_tot[tid - off] : 0.f;
        __syncthreads();
        s_tot[tid] += add;
    }
    __syncthreads();
    float excl = s_tot[tid] - total;

    float* out = g_cum + bh*TT;
    out[tid*4+0] = excl + r0;
    out[tid*4+1] = excl + r1;
    out[tid*4+2] = excl + r2;
    out[tid*4+3] = excl + r3;
}

// =================================================================================
// Kernel 3a: chunk moments P_k = B'^T @ X (unchanged)
// =================================================================================
#define KC_LDS 72
__global__ __launch_bounds__(256) void state_kernel()
{
    __shared__ __nv_bfloat16 Bp_h[64*KC_LDS], Bp_l[64*KC_LDS];
    __shared__ __nv_bfloat16 Xh_s[64*KC_LDS], Xl_s[64*KC_LDS];
    __shared__ float sc[64];

    const int k   = blockIdx.x;
    const int bh  = blockIdx.y;
    const int tid = threadIdx.x;
    const int w = tid >> 5, mrow = w & 3, nh = w >> 2;

    const uint32_t xh_b = smem_u32(Xh_s), xl_b = smem_u32(Xl_s);
#pragma unroll
    for (int s = 0; s < 4; ++s) {
        int l = tid + s*256;
        int tile = l >> 9, ww = l & 511, r = ww >> 3, q = ww & 7;
        const __nv_bfloat16* g = (tile ? g_Xl : g_Xh) + ((size_t)bh*TT + k*64 + r)*CH + q*8;
        cp16((tile ? xl_b : xh_b) + (uint32_t)(r*144 + q*16), g);
    }
    CP_COMMIT();
    if (tid < 64)
        sc[tid] = __expf(g_cum[bh*TT + k*64 + 63] - g_cum[bh*TT + k*64 + tid]);
    __syncthreads();

#pragma unroll
    for (int q = 0; q < 16; ++q) {
        int idx = tid + q*256;
        int ii = idx >> 6, jj = idx & 63;
        size_t go = ((size_t)bh*TT + k*64 + ii)*CH + jj;
        float v = (__bfloat162float(g_Bh[go]) + __bfloat162float(g_Bl[go])) * sc[ii];
        __nv_bfloat16 h = __float2bfloat16_rn(v);
        Bp_h[ii*KC_LDS + jj] = h;
        Bp_l[ii*KC_LDS + jj] = __float2bfloat16_rn(v - __bfloat162float(h));
    }
    CP_WAIT(0);
    __syncthreads();

    wmma::fragment<wmma::accumulator,16,16,16,float> pacc[2];
#pragma unroll
    for (int t2 = 0; t2 < 2; ++t2) wmma::fill_fragment(pacc[t2], 0.f);
#pragma unroll
    for (int kk = 0; kk < 4; ++kk) {
        wmma::fragment<wmma::matrix_a,16,16,16,__nv_bfloat16,wmma::col_major> aH, aL;
        wmma::load_matrix_sync(aH, &Bp_h[(kk*16)*KC_LDS + mrow*16], KC_LDS);
        wmma::load_matrix_sync(aL, &Bp_l[(kk*16)*KC_LDS + mrow*16], KC_LDS);
#pragma unroll
        for (int t2 = 0; t2 < 2; ++t2) {
            const int nt = nh*2 + t2;
            wmma::fragment<wmma::matrix_b,16,16,16,__nv_bfloat16,wmma::row_major> bH, bL;
            wmma::load_matrix_sync(bH, &Xh_s[(kk*16)*KC_LDS + nt*16], KC_LDS);
            wmma::load_matrix_sync(bL, &Xl_s[(kk*16)*KC_LDS + nt*16], KC_LDS);
            wmma::mma_sync(pacc[t2], aH, bH, pacc[t2]);
            wmma::mma_sync(pacc[t2], aH, bL, pacc[t2]);
            wmma::mma_sync(pacc[t2], aL, bH, pacc[t2]);
        }
    }
#pragma unroll
    for (int t2 = 0; t2 < 2; ++t2) {
        float* dst = g_P + ((size_t)bh*NCH + k)*4096 + (mrow*16)*64 + (nh*2+t2)*16;
        wmma::store_matrix_sync(dst, pacc[t2], 64, wmma::mem_row_major);
    }
}

// =================================================================================
// Kernel 3b: state scan (prefetched, unchanged)
// =================================================================================
__global__ __launch_bounds__(256) void scan_state()
{
    __shared__ float d[16];
    const int bh  = blockIdx.x;
    const int eb  = blockIdx.y * 512;
    const int tid = threadIdx.x;
    const int base = eb + tid*2;

    if (tid < 15) {
        float Ek = g_cum[bh*TT + tid*64 + 63];
        float Ep = (tid > 0) ? g_cum[bh*TT + tid*64 - 1] : 0.f;
        d[tid] = __expf(Ek - Ep);
    }

    float2 P[15];
#pragma unroll
    for (int k = 0; k < 15; ++k)
        P[k] = *(const float2*)&g_P[((size_t)bh*NCH + k)*4096 + base];
    __syncthreads();

    float2 S = make_float2(0.f, 0.f);
#pragma unroll
    for (int k = 0; k < 16; ++k) {
        size_t so = ((size_t)bh*NCH + k)*4096 + base;
        __nv_bfloat16 hx = __float2bfloat16_rn(S.x);
        __nv_bfloat16 hy = __float2bfloat16_rn(S.y);
        *(__nv_bfloat162*)(g_Sth + so) = __halves2bfloat162(hx, hy);
        *(__nv_bfloat162*)(g_Stl + so) = __halves2bfloat162(
            __float2bfloat16_rn(S.x - __bfloat162float(hx)),
            __float2bfloat16_rn(S.y - __bfloat162float(hy)));
        if (k < 15) {
            S.x = d[k]*S.x + P[k].x;
            S.y = d[k]*S.y + P[k].y;
        }
    }
}

// =================================================================================
// Kernel 3c: per-chunk output (unchanged)
// =================================================================================
#define AC_TILE (64*KC_LDS*2)
#define AC_S32A (8*AC_TILE)
#define AC_S32B (AC_S32A + 64*68*4)
#define AC_SCI  (AC_S32B + 64*68*4)
#define AC_SMEM (AC_SCI + 2*64*4)

__global__ __launch_bounds__(256) void attn_chunk()
{
    extern __shared__ __align__(128) char sm[];
    const uint32_t sbase = smem_u32(sm);
    __nv_bfloat16* Ch  = (__nv_bfloat16*)(sm);
    __nv_bfloat16* Cl  = (__nv_bfloat16*)(sm + 1*AC_TILE);
    __nv_bfloat16* Bh  = (__nv_bfloat16*)(sm + 2*AC_TILE);
    __nv_bfloat16* Bl  = (__nv_bfloat16*)(sm + 3*AC_TILE);
    __nv_bfloat16* Xh  = (__nv_bfloat16*)(sm + 4*AC_TILE);
    __nv_bfloat16* Xl  = (__nv_bfloat16*)(sm + 5*AC_TILE);
    __nv_bfloat16* Sth = (__nv_bfloat16*)(sm + 6*AC_TILE);
    __nv_bfloat16* Stl = (__nv_bfloat16*)(sm + 7*AC_TILE);
    float* S32a = (float*)(sm + AC_S32A);
    float* S32b = (float*)(sm + AC_S32B);
    float* sCi  = (float*)(sm + AC_SCI);
    float* sCj  = sCi + 64;

    const int k   = blockIdx.x;
    const int bh  = blockIdx.y;
    const int tid = threadIdx.x;
    const int w = tid >> 5, mrow = w & 3, nh = w >> 2;

    {
        const __nv_bfloat16* act[6] = {g_Chh, g_Cll, g_Bh, g_Bl, g_Xh, g_Xl};
#pragma unroll
        for (int s = 0; s < 12; ++s) {
            int l = tid + s*256;
            int tile = l >> 9, ww = l & 511, r = ww >> 3, q = ww & 7;
            const __nv_bfloat16* g = act[tile] + ((size_t)bh*TT + k*64 + r)*CH + q*8;
            cp16(sbase + (uint32_t)(tile*AC_TILE + r*144 + q*16), g);
        }
#pragma unroll
        for (int s = 0; s < 4; ++s) {
            int l = tid + s*256;
            int tile = l >> 9, ww = l & 511, r = ww >> 3, q = ww & 7;
            const __nv_bfloat16* g = (tile ? g_Stl : g_Sth) + ((size_t)bh*NCH + k)*4096 + r*64 + q*8;
            cp16(sbase + (uint32_t)((6+tile)*AC_TILE + r*144 + q*16), g);
        }
        CP_COMMIT();
    }
    {
        const float bk = (k > 0) ? g_cum[bh*TT + k*64 - 1] : 0.f;
        if (tid < 64)  sCi[tid] = __expf(g_cum[bh*TT + k*64 + tid] - bk);
        else if (tid < 128) sCj[tid-64] = __expf(bk - g_cum[bh*TT + k*64 + (tid-64)]);
    }
    CP_WAIT(0);
    __syncthreads();

    wmma::fragment<wmma::accumulator,16,16,16,float> sacc[2];
#pragma unroll
    for (int t2 = 0; t2 < 2; ++t2) wmma::fill_fragment(sacc[t2], 0.f);
#pragma unroll
    for (int kk = 0; kk < 4; ++kk) {
        wmma::fragment<wmma::matrix_a,16,16,16,__nv_bfloat16,wmma::row_major> aH, aL;
        wmma::load_matrix_sync(aH, &Ch[(mrow*16)*KC_LDS + kk*16], KC_LDS);
        wmma::load_matrix_sync(aL, &Cl[(mrow*16)*KC_LDS + kk*16], KC_LDS);
#pragma unroll
        for (int t2 = 0; t2 < 2; ++t2) {
            const int nt = nh*2 + t2;
            wmma::fragment<wmma::matrix_b,16,16,16,__nv_bfloat16,wmma::col_major> bH, bL;
            wmma::load_matrix_sync(bH, &Bh[(nt*16)*KC_LDS + kk*16], KC_LDS);
            wmma::load_matrix_sync(bL, &Bl[(nt*16)*KC_LDS + kk*16], KC_LDS);
            wmma::mma_sync(sacc[t2], aH, bH, sacc[t2]);
            wmma::mma_sync(sacc[t2], aH, bL, sacc[t2]);
            wmma::mma_sync(sacc[t2], aL, bH, sacc[t2]);
        }
    }
#pragma unroll
    for (int t2 = 0; t2 < 2; ++t2)
        wmma::store_matrix_sync(&S32a[(mrow*16)*68 + (nh*2+t2)*16], sacc[t2], 68,
                                wmma::mem_row_major);
    __syncthreads();

#pragma unroll
    for (int q = 0; q < 16; ++q) {
        int idx = (tid & 31) + q*32;
        int ii = mrow*16 + (idx >> 5);
        int jj = nh*32 + (idx & 31);
        float v = S32a[ii*68 + jj] * sCi[ii] * sCj[jj];
        if (jj > ii) v = 0.f;
        __nv_bfloat16 h = __float2bfloat16_rn(v);
        Bh[ii*KC_LDS + jj] = h;
        Bl[ii*KC_LDS + jj] = __float2bfloat16_rn(v - __bfloat162float(h));
    }
    __syncthreads();

    wmma::fragment<wmma::accumulator,16,16,16,float> yacc[2], zacc[2];
#pragma unroll
    for (int t2 = 0; t2 < 2; ++t2) { wmma::fill_fragment(yacc[t2], 0.f); wmma::fill_fragment(zacc[t2], 0.f); }
#pragma unroll
    for (int kk = 0; kk < 4; ++kk) {
        wmma::fragment<wmma::matrix_a,16,16,16,__nv_bfloat16,wmma::row_major> aH, aL, cH, cL;
        wmma::load_matrix_sync(aH, &Bh[(mrow*16)*KC_LDS + kk*16], KC_LDS);
        wmma::load_matrix_sync(aL, &Bl[(mrow*16)*KC_LDS + kk*16], KC_LDS);
        wmma::load_matrix_sync(cH, &Ch[(mrow*16)*KC_LDS + kk*16], KC_LDS);
        wmma::load_matrix_sync(cL, &Cl[(mrow*16)*KC_LDS + kk*16], KC_LDS);
#pragma unroll
        for (int t2 = 0; t2 < 2; ++t2) {
            const int ct = nh*2 + t2;
            wmma::fragment<wmma::matrix_b,16,16,16,__nv_bfloat16,wmma::row_major> bH, bL, sH, sL;
            wmma::load_matrix_sync(bH, &Xh[(kk*16)*KC_LDS + ct*16], KC_LDS);
            wmma::load_matrix_sync(bL, &Xl[(kk*16)*KC_LDS + ct*16], KC_LDS);
            wmma::mma_sync(yacc[t2], aH, bH, yacc[t2]);
            wmma::mma_sync(yacc[t2], aH, bL, yacc[t2]);
            wmma::mma_sync(yacc[t2], aL, bH, yacc[t2]);
            wmma::load_matrix_sync(sH, &Sth[(kk*16)*KC_LDS + ct*16], KC_LDS);
            wmma::load_matrix_sync(sL, &Stl[(kk*16)*KC_LDS + ct*16], KC_LDS);
            wmma::mma_sync(zacc[t2], cH, sH, zacc[t2]);
            wmma::mma_sync(zacc[t2], cH, sL, zacc[t2]);
            wmma::mma_sync(zacc[t2], cL, sH, zacc[t2]);
        }
    }
#pragma unroll
    for (int t2 = 0; t2 < 2; ++t2) {
        wmma::store_matrix_sync(&S32a[(mrow*16)*68 + (nh*2+t2)*16], yacc[t2], 68, wmma::mem_row_major);
        wmma::store_matrix_sync(&S32b[(mrow*16)*68 + (nh*2+t2)*16], zacc[t2], 68, wmma::mem_row_major);
    }
    __syncwarp();

    const int b_ = bh >> 4, h = bh & 15;
#pragma unroll
    for (int q = 0; q < 16; ++q) {
        int idx = (tid & 31) + q*32;
        int ii = mrow*16 + (idx >> 5);
        int cc = nh*32 + (idx & 31);
        float y = S32a[ii*68 + cc] + sCi[ii] * S32b[ii*68 + cc];
        float v = y * g_gate[((size_t)bh*TT + k*64 + ii)*CH + cc];
        size_t o = ((size_t)b_*TT + k*64 + ii)*DD + h*CH + cc;
        __nv_bfloat16 hh = __float2bfloat16_rn(v);
        g_YgH[o] = hh;
        g_YgL[o] = __float2bfloat16_rn(v - __bfloat162float(hh));
    }
}

// =================================================================================
// out_gemm_wmma: 512 threads / 16 warps, 3-stage cp.async pipeline (depth 2).
// =================================================================================
#define NCHUNK   32
#define TILE_B   10240
#define STAGE_B  (4*TILE_B)            // 40960
#define BIAS_OFF (3*STAGE_B)           // 122880
#define OG_SMEM  (BIAS_OFF + 16*128*4) // 131072

__global__ __launch_bounds__(512) void out_gemm_wmma(
    const float* __restrict__ b_out, float* __restrict__ out)
{
    extern __shared__ __align__(128) char smem[];
    const uint32_t sbase = smem_u32(smem);
    __nv_bfloat16* s_bf = (__nv_bfloat16*)smem;
    float* bias_s = (float*)(smem + BIAS_OFF);

    const int tid  = threadIdx.x;
    const int wid  = tid >> 5;
    const int warpM = wid & 3;
    const int warpN = wid >> 2;
    const int mb = blockIdx.x * 128;
    const int nb = blockIdx.y * 128;

    const __nv_bfloat16* __restrict__ srcs[4] = {g_YgH, g_YgL, g_WH, g_WL};

    auto issue_stage = [&](int chunk) {
        const int kc = chunk * 32;
        const uint32_t sb = sbase + (uint32_t)(chunk % 3) * STAGE_B;
#pragma unroll
        for (int s = 0; s < 4; ++s) {
            const int l = tid + s * 512;
            const int tile = l >> 9;
            const int w = l & 511;
            const int r = w >> 2;
            const int q = w & 3;
            const int grow = (tile < 2 ? mb : nb) + r;
            const __nv_bfloat16* g = srcs[tile] + (size_t)grow * DD + kc + q * 8;
            cp16(sb + tile * TILE_B + r * 80 + q * 16, g);
        }
        CP_COMMIT();
    };

    issue_stage(0);
    issue_stage(1);

    for (int i = tid; i < 16*128; i += 512) bias_s[i] = b_out[nb + (i & 127)];
    __syncthreads();   // bias visible (also pre-loop barrier)

    wmma::fragment<wmma::accumulator, 16, 16, 16, float> acc[2][2];
#pragma unroll
    for (int mt = 0; mt < 2; ++mt)
#pragma unroll
        for (int nt = 0; nt < 2; ++nt)
            wmma::load_matrix_sync(acc[mt][nt], &bias_s[warpN*32 + nt*16], 128,
                                   wmma::mem_row_major);

    for (int c = 0; c < NCHUNK; ++c) {
        if (c + 2 < NCHUNK) { issue_stage(c + 2); CP_WAIT(2); }
        else if (c + 1 < NCHUNK) { CP_WAIT(1); }
        else { CP_WAIT(0); }
        __syncthreads();   // stage c data visible to all warps

        __nv_bfloat16* sAH = s_bf + (size_t)(c % 3) * (STAGE_B/2);
        __nv_bfloat16* sAL = sAH + TILE_B/2;
        __nv_bfloat16* sBH = sAH + TILE_B;
        __nv_bfloat16* sBL = sAH + 3*(TILE_B/2);

#pragma unroll
        for (int ks = 0; ks < 2; ++ks) {
            wmma::fragment<wmma::matrix_a, 16, 16, 16, __nv_bfloat16, wmma::row_major> aH[2], aL[2];
#pragma unroll
            for (int mt = 0; mt < 2; ++mt) {
                wmma::load_matrix_sync(aH[mt], &sAH[(warpM*32 + mt*16)*40 + ks*16], 40);
                wmma::load_matrix_sync(aL[mt], &sAL[(warpM*32 + mt*16)*40 + ks*16], 40);
            }
#pragma unroll
            for (int nt = 0; nt < 2; ++nt) {
                wmma::fragment<wmma::matrix_b, 16, 16, 16, __nv_bfloat16, wmma::col_major> bH, bL;
                wmma::load_matrix_sync(bH, &sBH[(warpN*32 + nt*16)*40 + ks*16], 40);
                wmma::load_matrix_sync(bL, &sBL[(warpN*32 + nt*16)*40 + ks*16], 40);
#pragma unroll
                for (int mt = 0; mt < 2; ++mt) {
                    wmma::mma_sync(acc[mt][nt], aH[mt], bH, acc[mt][nt]);
                    wmma::mma_sync(acc[mt][nt], aH[mt], bL, acc[mt][nt]);
                    wmma::mma_sync(acc[mt][nt], aL[mt], bH, acc[mt][nt]);
                }
            }
        }
        __syncthreads();   // all warps done with buffer (c%3) before refill
    }

#pragma unroll
    for (int mt = 0; mt < 2; ++mt)
#pragma unroll
        for (int nt = 0; nt < 2; ++nt) {
            float* dst = out + (size_t)(mb + warpM*32 + mt*16) * DD + nb + warpN*32 + nt*16;
            wmma::store_matrix_sync(dst, acc[mt][nt], DD, wmma::mem_row_major);
        }
}

// =================================================================================
extern "C" void kernel_launch(void* const* d_in, const int* in_sizes, int n_in,
                              void* d_out, int out_size)
{
    const float* inp    = (const float*)d_in[0];
    const float* W_logA = (const float*)d_in[1];
    const float* b_logA = (const float*)d_in[2];
    const float* W_XBC  = (const float*)d_in[3];
    const float* b_XBC  = (const float*)d_in[4];
    const float* W_gate = (const float*)d_in[5];
    const float* b_gate = (const float*)d_in[6];
    const float* W_out  = (const float*)d_in[7];
    const float* b_out  = (const float*)d_in[8];
    float* out = (float*)d_out;

    proj_kernel<<<dim3(32, 4, 16), 128>>>(inp, W_XBC, b_XBC, W_gate, b_gate);
    scan_cvt_kernel<<<1056, 256>>>(inp, W_logA, b_logA, W_out);

    state_kernel<<<dim3(NCH-1, BHN), 256>>>();
    scan_state<<<dim3(BHN, 8), 256>>>();

    cudaFuncSetAttribute(attn_chunk, cudaFuncAttributeMaxDynamicSharedMemorySize, AC_SMEM);
    attn_chunk<<<dim3(NCH, BHN), 256, AC_SMEM>>>();

    cudaFuncSetAttribute(out_gemm_wmma, cudaFuncAttributeMaxDynamicSharedMemorySize, OG_SMEM);
    out_gemm_wmma<<<dim3(16, 8), 512, OG_SMEM>>>(b_out, out);
}

// round 14
// speedup vs baseline: 1.6202x; 1.6202x over previous
#include <cuda_runtime.h>
#include <cuda_bf16.h>
#include <mma.h>
#include <math.h>
#include <cstdint>

using namespace nvcuda;

#define BB 2
#define TT 1024
#define DD 1024
#define HH 16
#define CH 64
#define BHN (BB*HH)
#define NCH 16

// ---------------- device scratch ----------------
__device__ __align__(128) float g_cum [BHN*TT];
__device__ __align__(128) float g_gate[BHN*TT*CH];

// bf16 hi/lo activations (written directly by proj_kernel)
__device__ __align__(128) __nv_bfloat16 g_Xh[BHN*TT*CH];
__device__ __align__(128) __nv_bfloat16 g_Xl[BHN*TT*CH];
__device__ __align__(128) __nv_bfloat16 g_Bh[BHN*TT*CH];
__device__ __align__(128) __nv_bfloat16 g_Bl[BHN*TT*CH];
__device__ __align__(128) __nv_bfloat16 g_Chh[BHN*TT*CH];
__device__ __align__(128) __nv_bfloat16 g_Cll[BHN*TT*CH];

// chunked-scan intermediates
__device__ __align__(128) float         g_P  [BHN*NCH*64*64];
__device__ __align__(128) __nv_bfloat16 g_Sth[BHN*NCH*64*64];
__device__ __align__(128) __nv_bfloat16 g_Stl[BHN*NCH*64*64];

// output GEMM operands
__device__ __align__(128) __nv_bfloat16 g_YgH[BB*TT*DD];
__device__ __align__(128) __nv_bfloat16 g_YgL[BB*TT*DD];
__device__ __align__(128) __nv_bfloat16 g_WH [DD*DD];
__device__ __align__(128) __nv_bfloat16 g_WL [DD*DD];

// ---------------- helpers ----------------
__device__ __forceinline__ uint32_t smem_u32(const void* p) {
    uint32_t a;
    asm("{ .reg .u64 t; cvta.to.shared.u64 t, %1; cvt.u32.u64 %0, t; }" : "=r"(a) : "l"(p));
    return a;
}
__device__ __forceinline__ void cp16(uint32_t dst, const void* src) {
    asm volatile("cp.async.cg.shared.global [%0], [%1], 16;" :: "r"(dst), "l"(src) : "memory");
}
#define CP_COMMIT() asm volatile("cp.async.commit_group;" ::: "memory")
#define CP_WAIT(n)  asm volatile("cp.async.wait_group %0;" :: "n"(n) : "memory")

// =================================================================================
// Kernel 1: fused per-head projections (fp32 FFMA). 256 outputs = 4 o-tiles.
// Also folds the W_out fp32->bf16 hi/lo split: 2048 CTAs x 512 floats rides in
// proj's idle memory pipe (proj is FFMA-issue-bound, DRAM ~3%).
// =================================================================================
__global__ __launch_bounds__(128) void proj_kernel(
    const float* __restrict__ inp,
    const float* __restrict__ W_XBC,  const float* __restrict__ b_XBC,
    const float* __restrict__ W_gate, const float* __restrict__ b_gate,
    const float* __restrict__ W_out)
{
    __shared__ float As[64*68];
    __shared__ float Ws[64*68];

    const int h     = blockIdx.z;
    const int mbase = blockIdx.x * 64;
    const int obase = blockIdx.y * 64;
    const int tid   = threadIdx.x;

    // ---- folded W_out cvt: one float4 per thread ----
    {
        const int bid = blockIdx.x + 32*blockIdx.y + 128*blockIdx.z;  // 0..2047
        const int i   = bid * 128 + tid;                              // float4 index < 262144
        float4 v = ((const float4*)W_out)[i];
        float x[4] = {v.x, v.y, v.z, v.w};
        __nv_bfloat16 hh[4], ll[4];
#pragma unroll
        for (int k = 0; k < 4; ++k) {
            hh[k] = __float2bfloat16_rn(x[k]);
            ll[k] = __float2bfloat16_rn(x[k] - __bfloat162float(hh[k]));
        }
        ((__nv_bfloat162*)g_WH)[i*2+0] = __halves2bfloat162(hh[0], hh[1]);
        ((__nv_bfloat162*)g_WH)[i*2+1] = __halves2bfloat162(hh[2], hh[3]);
        ((__nv_bfloat162*)g_WL)[i*2+0] = __halves2bfloat162(ll[0], ll[1]);
        ((__nv_bfloat162*)g_WL)[i*2+1] = __halves2bfloat162(ll[2], ll[3]);
    }

    for (int l4 = tid; l4 < 64*16; l4 += 128) {
        int r = l4 >> 4, c4 = l4 & 15;
        float4 v = *(const float4*)&inp[(size_t)(mbase + r) * DD + h*CH + c4*4];
        *(float4*)&As[r*68 + c4*4] = v;
    }
    for (int l4 = tid; l4 < 64*16; l4 += 128) {
        int r = l4 >> 4, c4 = l4 & 15;
        int o = obase + r;
        float4 v;
        if (o < 192) v = *(const float4*)&W_XBC[((size_t)(h*192) + o)*CH + c4*4];
        else         v = *(const float4*)&W_gate[((size_t)(h*CH) + (o-192))*CH + c4*4];
        *(float4*)&Ws[r*68 + c4*4] = v;
    }
    __syncthreads();

    const int ty = tid >> 4, tx = tid & 15;
    float acc[8][4];
#pragma unroll
    for (int i = 0; i < 8; ++i)
#pragma unroll
        for (int j = 0; j < 4; ++j) acc[i][j] = 0.f;

#pragma unroll
    for (int k4 = 0; k4 < 16; ++k4) {
        float4 a[8], b[4];
#pragma unroll
        for (int i = 0; i < 8; ++i) a[i] = *(float4*)&As[(ty + 8*i)*68 + k4*4];
#pragma unroll
        for (int j = 0; j < 4; ++j) b[j] = *(float4*)&Ws[(tx + 16*j)*68 + k4*4];
#pragma unroll
        for (int i = 0; i < 8; ++i)
#pragma unroll
            for (int j = 0; j < 4; ++j) {
                acc[i][j] += a[i].x*b[j].x;
                acc[i][j] += a[i].y*b[j].y;
                acc[i][j] += a[i].z*b[j].z;
                acc[i][j] += a[i].w*b[j].w;
            }
    }

#pragma unroll
    for (int i = 0; i < 8; ++i) {
#pragma unroll
        for (int j = 0; j < 4; ++j) {
            int o  = obase + tx + 16*j;
            int m  = mbase + ty + 8*i;
            int b_ = m >> 10;
            int t  = m & (TT-1);
            int bh = b_*HH + h;
            float v = acc[i][j];
            if (o < 192) {
                float z = v + b_XBC[h*192 + o];
                float s = z / (1.f + __expf(-z));
                __nv_bfloat16 hi = __float2bfloat16_rn(s);
                __nv_bfloat16 lo = __float2bfloat16_rn(s - __bfloat162float(hi));
                size_t idx;
                if (o < 64)       { idx = ((size_t)bh*TT + t)*CH + o;       g_Xh[idx]=hi; g_Xl[idx]=lo; }
                else if (o < 128) { idx = ((size_t)bh*TT + t)*CH + (o-64);  g_Bh[idx]=hi; g_Bl[idx]=lo; }
                else              { idx = ((size_t)bh*TT + t)*CH + (o-128); g_Chh[idx]=hi; g_Cll[idx]=lo; }
            } else {
                g_gate[((size_t)bh*TT + t)*CH + (o-192)] = v + b_gate[h*CH + (o-192)];
            }
        }
    }
}

// =================================================================================
// Kernel 2: fused logA GEMV + inclusive cumsum (R12 version)
// =================================================================================
__global__ __launch_bounds__(256) void scan_kernel(
    const float* __restrict__ inp,
    const float* __restrict__ W_logA, const float* __restrict__ b_logA)
{
    __shared__ float s_tot[256];
    __shared__ float w[64];
    const int bh  = blockIdx.x;
    const int b_  = bh >> 4, h = bh & 15;
    const int tid = threadIdx.x;

    if (tid < 64) w[tid] = W_logA[h*CH + tid];
    __syncthreads();
    const float bA = b_logA[h];

    float v[4];
#pragma unroll
    for (int j = 0; j < 4; ++j) {
        const int t = tid*4 + j;
        const float4* row = (const float4*)&inp[((size_t)b_*TT + t)*DD + h*CH];
        float dot = 0.f;
#pragma unroll
        for (int c4 = 0; c4 < 16; ++c4) {
            float4 x = row[c4];
            dot += x.x*w[c4*4+0] + x.y*w[c4*4+1] + x.z*w[c4*4+2] + x.w*w[c4*4+3];
        }
        v[j] = dot + bA;
    }

    float r0 = v[0], r1 = r0+v[1], r2 = r1+v[2], r3 = r2+v[3];
    float total = r3;
    s_tot[tid] = r3;

    for (int off = 1; off < 256; off <<= 1) {
        __syncthreads();
        float add = (tid >= off) ? s_tot[tid - off] : 0.f;
        __syncthreads();
        s_tot[tid] += add;
    }
    __syncthreads();
    float excl = s_tot[tid] - total;

    float* out = g_cum + bh*TT;
    out[tid*4+0] = excl + r0;
    out[tid*4+1] = excl + r1;
    out[tid*4+2] = excl + r2;
    out[tid*4+3] = excl + r3;
}

// =================================================================================
// Kernel 3a: chunk moments P_k = B'^T @ X (unchanged)
// =================================================================================
#define KC_LDS 72
__global__ __launch_bounds__(256) void state_kernel()
{
    __shared__ __nv_bfloat16 Bp_h[64*KC_LDS], Bp_l[64*KC_LDS];
    __shared__ __nv_bfloat16 Xh_s[64*KC_LDS], Xl_s[64*KC_LDS];
    __shared__ float sc[64];

    const int k   = blockIdx.x;
    const int bh  = blockIdx.y;
    const int tid = threadIdx.x;
    const int w = tid >> 5, mrow = w & 3, nh = w >> 2;

    const uint32_t xh_b = smem_u32(Xh_s), xl_b = smem_u32(Xl_s);
#pragma unroll
    for (int s = 0; s < 4; ++s) {
        int l = tid + s*256;
        int tile = l >> 9, ww = l & 511, r = ww >> 3, q = ww & 7;
        const __nv_bfloat16* g = (tile ? g_Xl : g_Xh) + ((size_t)bh*TT + k*64 + r)*CH + q*8;
        cp16((tile ? xl_b : xh_b) + (uint32_t)(r*144 + q*16), g);
    }
    CP_COMMIT();
    if (tid < 64)
        sc[tid] = __expf(g_cum[bh*TT + k*64 + 63] - g_cum[bh*TT + k*64 + tid]);
    __syncthreads();

#pragma unroll
    for (int q = 0; q < 16; ++q) {
        int idx = tid + q*256;
        int ii = idx >> 6, jj = idx & 63;
        size_t go = ((size_t)bh*TT + k*64 + ii)*CH + jj;
        float v = (__bfloat162float(g_Bh[go]) + __bfloat162float(g_Bl[go])) * sc[ii];
        __nv_bfloat16 h = __float2bfloat16_rn(v);
        Bp_h[ii*KC_LDS + jj] = h;
        Bp_l[ii*KC_LDS + jj] = __float2bfloat16_rn(v - __bfloat162float(h));
    }
    CP_WAIT(0);
    __syncthreads();

    wmma::fragment<wmma::accumulator,16,16,16,float> pacc[2];
#pragma unroll
    for (int t2 = 0; t2 < 2; ++t2) wmma::fill_fragment(pacc[t2], 0.f);
#pragma unroll
    for (int kk = 0; kk < 4; ++kk) {
        wmma::fragment<wmma::matrix_a,16,16,16,__nv_bfloat16,wmma::col_major> aH, aL;
        wmma::load_matrix_sync(aH, &Bp_h[(kk*16)*KC_LDS + mrow*16], KC_LDS);
        wmma::load_matrix_sync(aL, &Bp_l[(kk*16)*KC_LDS + mrow*16], KC_LDS);
#pragma unroll
        for (int t2 = 0; t2 < 2; ++t2) {
            const int nt = nh*2 + t2;
            wmma::fragment<wmma::matrix_b,16,16,16,__nv_bfloat16,wmma::row_major> bH, bL;
            wmma::load_matrix_sync(bH, &Xh_s[(kk*16)*KC_LDS + nt*16], KC_LDS);
            wmma::load_matrix_sync(bL, &Xl_s[(kk*16)*KC_LDS + nt*16], KC_LDS);
            wmma::mma_sync(pacc[t2], aH, bH, pacc[t2]);
            wmma::mma_sync(pacc[t2], aH, bL, pacc[t2]);
            wmma::mma_sync(pacc[t2], aL, bH, pacc[t2]);
        }
    }
#pragma unroll
    for (int t2 = 0; t2 < 2; ++t2) {
        float* dst = g_P + ((size_t)bh*NCH + k)*4096 + (mrow*16)*64 + (nh*2+t2)*16;
        wmma::store_matrix_sync(dst, pacc[t2], 64, wmma::mem_row_major);
    }
}

// =================================================================================
// Kernel 3b: state scan (prefetched, unchanged)
// =================================================================================
__global__ __launch_bounds__(256) void scan_state()
{
    __shared__ float d[16];
    const int bh  = blockIdx.x;
    const int eb  = blockIdx.y * 512;
    const int tid = threadIdx.x;
    const int base = eb + tid*2;

    if (tid < 15) {
        float Ek = g_cum[bh*TT + tid*64 + 63];
        float Ep = (tid > 0) ? g_cum[bh*TT + tid*64 - 1] : 0.f;
        d[tid] = __expf(Ek - Ep);
    }

    float2 P[15];
#pragma unroll
    for (int k = 0; k < 15; ++k)
        P[k] = *(const float2*)&g_P[((size_t)bh*NCH + k)*4096 + base];
    __syncthreads();

    float2 S = make_float2(0.f, 0.f);
#pragma unroll
    for (int k = 0; k < 16; ++k) {
        size_t so = ((size_t)bh*NCH + k)*4096 + base;
        __nv_bfloat16 hx = __float2bfloat16_rn(S.x);
        __nv_bfloat16 hy = __float2bfloat16_rn(S.y);
        *(__nv_bfloat162*)(g_Sth + so) = __halves2bfloat162(hx, hy);
        *(__nv_bfloat162*)(g_Stl + so) = __halves2bfloat162(
            __float2bfloat16_rn(S.x - __bfloat162float(hx)),
            __float2bfloat16_rn(S.y - __bfloat162float(hy)));
        if (k < 15) {
            S.x = d[k]*S.x + P[k].x;
            S.y = d[k]*S.y + P[k].y;
        }
    }
}

// =================================================================================
// Kernel 3c: per-chunk output (unchanged)
// =================================================================================
#define AC_TILE (64*KC_LDS*2)
#define AC_S32A (8*AC_TILE)
#define AC_S32B (AC_S32A + 64*68*4)
#define AC_SCI  (AC_S32B + 64*68*4)
#define AC_SMEM (AC_SCI + 2*64*4)

__global__ __launch_bounds__(256) void attn_chunk()
{
    extern __shared__ __align__(128) char sm[];
    const uint32_t sbase = smem_u32(sm);
    __nv_bfloat16* Ch  = (__nv_bfloat16*)(sm);
    __nv_bfloat16* Cl  = (__nv_bfloat16*)(sm + 1*AC_TILE);
    __nv_bfloat16* Bh  = (__nv_bfloat16*)(sm + 2*AC_TILE);
    __nv_bfloat16* Bl  = (__nv_bfloat16*)(sm + 3*AC_TILE);
    __nv_bfloat16* Xh  = (__nv_bfloat16*)(sm + 4*AC_TILE);
    __nv_bfloat16* Xl  = (__nv_bfloat16*)(sm + 5*AC_TILE);
    __nv_bfloat16* Sth = (__nv_bfloat16*)(sm + 6*AC_TILE);
    __nv_bfloat16* Stl = (__nv_bfloat16*)(sm + 7*AC_TILE);
    float* S32a = (float*)(sm + AC_S32A);
    float* S32b = (float*)(sm + AC_S32B);
    float* sCi  = (float*)(sm + AC_SCI);
    float* sCj  = sCi + 64;

    const int k   = blockIdx.x;
    const int bh  = blockIdx.y;
    const int tid = threadIdx.x;
    const int w = tid >> 5, mrow = w & 3, nh = w >> 2;

    {
        const __nv_bfloat16* act[6] = {g_Chh, g_Cll, g_Bh, g_Bl, g_Xh, g_Xl};
#pragma unroll
        for (int s = 0; s < 12; ++s) {
            int l = tid + s*256;
            int tile = l >> 9, ww = l & 511, r = ww >> 3, q = ww & 7;
            const __nv_bfloat16* g = act[tile] + ((size_t)bh*TT + k*64 + r)*CH + q*8;
            cp16(sbase + (uint32_t)(tile*AC_TILE + r*144 + q*16), g);
        }
#pragma unroll
        for (int s = 0; s < 4; ++s) {
            int l = tid + s*256;
            int tile = l >> 9, ww = l & 511, r = ww >> 3, q = ww & 7;
            const __nv_bfloat16* g = (tile ? g_Stl : g_Sth) + ((size_t)bh*NCH + k)*4096 + r*64 + q*8;
            cp16(sbase + (uint32_t)((6+tile)*AC_TILE + r*144 + q*16), g);
        }
        CP_COMMIT();
    }
    {
        const float bk = (k > 0) ? g_cum[bh*TT + k*64 - 1] : 0.f;
        if (tid < 64)  sCi[tid] = __expf(g_cum[bh*TT + k*64 + tid] - bk);
        else if (tid < 128) sCj[tid-64] = __expf(bk - g_cum[bh*TT + k*64 + (tid-64)]);
    }
    CP_WAIT(0);
    __syncthreads();

    wmma::fragment<wmma::accumulator,16,16,16,float> sacc[2];
#pragma unroll
    for (int t2 = 0; t2 < 2; ++t2) wmma::fill_fragment(sacc[t2], 0.f);
#pragma unroll
    for (int kk = 0; kk < 4; ++kk) {
        wmma::fragment<wmma::matrix_a,16,16,16,__nv_bfloat16,wmma::row_major> aH, aL;
        wmma::load_matrix_sync(aH, &Ch[(mrow*16)*KC_LDS + kk*16], KC_LDS);
        wmma::load_matrix_sync(aL, &Cl[(mrow*16)*KC_LDS + kk*16], KC_LDS);
#pragma unroll
        for (int t2 = 0; t2 < 2; ++t2) {
            const int nt = nh*2 + t2;
            wmma::fragment<wmma::matrix_b,16,16,16,__nv_bfloat16,wmma::col_major> bH, bL;
            wmma::load_matrix_sync(bH, &Bh[(nt*16)*KC_LDS + kk*16], KC_LDS);
            wmma::load_matrix_sync(bL, &Bl[(nt*16)*KC_LDS + kk*16], KC_LDS);
            wmma::mma_sync(sacc[t2], aH, bH, sacc[t2]);
            wmma::mma_sync(sacc[t2], aH, bL, sacc[t2]);
            wmma::mma_sync(sacc[t2], aL, bH, sacc[t2]);
        }
    }
#pragma unroll
    for (int t2 = 0; t2 < 2; ++t2)
        wmma::store_matrix_sync(&S32a[(mrow*16)*68 + (nh*2+t2)*16], sacc[t2], 68,
                                wmma::mem_row_major);
    __syncthreads();

#pragma unroll
    for (int q = 0; q < 16; ++q) {
        int idx = (tid & 31) + q*32;
        int ii = mrow*16 + (idx >> 5);
        int jj = nh*32 + (idx & 31);
        float v = S32a[ii*68 + jj] * sCi[ii] * sCj[jj];
        if (jj > ii) v = 0.f;
        __nv_bfloat16 h = __float2bfloat16_rn(v);
        Bh[ii*KC_LDS + jj] = h;
        Bl[ii*KC_LDS + jj] = __float2bfloat16_rn(v - __bfloat162float(h));
    }
    __syncthreads();

    wmma::fragment<wmma::accumulator,16,16,16,float> yacc[2], zacc[2];
#pragma unroll
    for (int t2 = 0; t2 < 2; ++t2) { wmma::fill_fragment(yacc[t2], 0.f); wmma::fill_fragment(zacc[t2], 0.f); }
#pragma unroll
    for (int kk = 0; kk < 4; ++kk) {
        wmma::fragment<wmma::matrix_a,16,16,16,__nv_bfloat16,wmma::row_major> aH, aL, cH, cL;
        wmma::load_matrix_sync(aH, &Bh[(mrow*16)*KC_LDS + kk*16], KC_LDS);
        wmma::load_matrix_sync(aL, &Bl[(mrow*16)*KC_LDS + kk*16], KC_LDS);
        wmma::load_matrix_sync(cH, &Ch[(mrow*16)*KC_LDS + kk*16], KC_LDS);
        wmma::load_matrix_sync(cL, &Cl[(mrow*16)*KC_LDS + kk*16], KC_LDS);
#pragma unroll
        for (int t2 = 0; t2 < 2; ++t2) {
            const int ct = nh*2 + t2;
            wmma::fragment<wmma::matrix_b,16,16,16,__nv_bfloat16,wmma::row_major> bH, bL, sH, sL;
            wmma::load_matrix_sync(bH, &Xh[(kk*16)*KC_LDS + ct*16], KC_LDS);
            wmma::load_matrix_sync(bL, &Xl[(kk*16)*KC_LDS + ct*16], KC_LDS);
            wmma::mma_sync(yacc[t2], aH, bH, yacc[t2]);
            wmma::mma_sync(yacc[t2], aH, bL, yacc[t2]);
            wmma::mma_sync(yacc[t2], aL, bH, yacc[t2]);
            wmma::load_matrix_sync(sH, &Sth[(kk*16)*KC_LDS + ct*16], KC_LDS);
            wmma::load_matrix_sync(sL, &Stl[(kk*16)*KC_LDS + ct*16], KC_LDS);
            wmma::mma_sync(zacc[t2], cH, sH, zacc[t2]);
            wmma::mma_sync(zacc[t2], cH, sL, zacc[t2]);
            wmma::mma_sync(zacc[t2], cL, sH, zacc[t2]);
        }
    }
#pragma unroll
    for (int t2 = 0; t2 < 2; ++t2) {
        wmma::store_matrix_sync(&S32a[(mrow*16)*68 + (nh*2+t2)*16], yacc[t2], 68, wmma::mem_row_major);
        wmma::store_matrix_sync(&S32b[(mrow*16)*68 + (nh*2+t2)*16], zacc[t2], 68, wmma::mem_row_major);
    }
    __syncwarp();

    const int b_ = bh >> 4, h = bh & 15;
#pragma unroll
    for (int q = 0; q < 16; ++q) {
        int idx = (tid & 31) + q*32;
        int ii = mrow*16 + (idx >> 5);
        int cc = nh*32 + (idx & 31);
        float y = S32a[ii*68 + cc] + sCi[ii] * S32b[ii*68 + cc];
        float v = y * g_gate[((size_t)bh*TT + k*64 + ii)*CH + cc];
        size_t o = ((size_t)b_*TT + k*64 + ii)*DD + h*CH + cc;
        __nv_bfloat16 hh = __float2bfloat16_rn(v);
        g_YgH[o] = hh;
        g_YgL[o] = __float2bfloat16_rn(v - __bfloat162float(hh));
    }
}

// =================================================================================
// out_gemm_wmma: 512 threads / 16 warps, 2-stage cp.async double buffer (R12).
// =================================================================================
#define NCHUNK   32
#define TILE_B   10240
#define STAGE_B  (4*TILE_B)
#define BIAS_OFF (2*STAGE_B)
#define OG_SMEM  (BIAS_OFF + 16*128*4)

__global__ __launch_bounds__(512) void out_gemm_wmma(
    const float* __restrict__ b_out, float* __restrict__ out)
{
    extern __shared__ __align__(128) char smem[];
    const uint32_t sbase = smem_u32(smem);
    __nv_bfloat16* s_bf = (__nv_bfloat16*)smem;
    float* bias_s = (float*)(smem + BIAS_OFF);

    const int tid  = threadIdx.x;
    const int wid  = tid >> 5;
    const int warpM = wid & 3;
    const int warpN = wid >> 2;
    const int mb = blockIdx.x * 128;
    const int nb = blockIdx.y * 128;

    const __nv_bfloat16* __restrict__ srcs[4] = {g_YgH, g_YgL, g_WH, g_WL};

    auto issue_stage = [&](int chunk, int p) {
        const int kc = chunk * 32;
        const uint32_t sb = sbase + (uint32_t)p * STAGE_B;
#pragma unroll
        for (int s = 0; s < 4; ++s) {
            const int l = tid + s * 512;
            const int tile = l >> 9;
            const int w = l & 511;
            const int r = w >> 2;
            const int q = w & 3;
            const int grow = (tile < 2 ? mb : nb) + r;
            const __nv_bfloat16* g = srcs[tile] + (size_t)grow * DD + kc + q * 8;
            cp16(sb + tile * TILE_B + r * 80 + q * 16, g);
        }
        CP_COMMIT();
    };

    issue_stage(0, 0);

    for (int i = tid; i < 16*128; i += 512) bias_s[i] = b_out[nb + (i & 127)];
    __syncthreads();

    wmma::fragment<wmma::accumulator, 16, 16, 16, float> acc[2][2];
#pragma unroll
    for (int mt = 0; mt < 2; ++mt)
#pragma unroll
        for (int nt = 0; nt < 2; ++nt)
            wmma::load_matrix_sync(acc[mt][nt], &bias_s[warpN*32 + nt*16], 128,
                                   wmma::mem_row_major);

    for (int c = 0; c < NCHUNK; ++c) {
        const int p = c & 1;
        if (c + 1 < NCHUNK) { issue_stage(c + 1, p ^ 1); CP_WAIT(1); }
        else                { CP_WAIT(0); }
        __syncthreads();

        __nv_bfloat16* sAH = s_bf + (size_t)p * (STAGE_B/2);
        __nv_bfloat16* sAL = sAH + TILE_B/2;
        __nv_bfloat16* sBH = sAH + TILE_B;
        __nv_bfloat16* sBL = sAH + 3*(TILE_B/2);

#pragma unroll
        for (int ks = 0; ks < 2; ++ks) {
            wmma::fragment<wmma::matrix_a, 16, 16, 16, __nv_bfloat16, wmma::row_major> aH[2], aL[2];
#pragma unroll
            for (int mt = 0; mt < 2; ++mt) {
                wmma::load_matrix_sync(aH[mt], &sAH[(warpM*32 + mt*16)*40 + ks*16], 40);
                wmma::load_matrix_sync(aL[mt], &sAL[(warpM*32 + mt*16)*40 + ks*16], 40);
            }
#pragma unroll
            for (int nt = 0; nt < 2; ++nt) {
                wmma::fragment<wmma::matrix_b, 16, 16, 16, __nv_bfloat16, wmma::col_major> bH, bL;
                wmma::load_matrix_sync(bH, &sBH[(warpN*32 + nt*16)*40 + ks*16], 40);
                wmma::load_matrix_sync(bL, &sBL[(warpN*32 + nt*16)*40 + ks*16], 40);
#pragma unroll
                for (int mt = 0; mt < 2; ++mt) {
                    wmma::mma_sync(acc[mt][nt], aH[mt], bH, acc[mt][nt]);
                    wmma::mma_sync(acc[mt][nt], aH[mt], bL, acc[mt][nt]);
                    wmma::mma_sync(acc[mt][nt], aL[mt], bH, acc[mt][nt]);
                }
            }
        }
        __syncthreads();
    }

#pragma unroll
    for (int mt = 0; mt < 2; ++mt)
#pragma unroll
        for (int nt = 0; nt < 2; ++nt) {
            float* dst = out + (size_t)(mb + warpM*32 + mt*16) * DD + nb + warpN*32 + nt*16;
            wmma::store_matrix_sync(dst, acc[mt][nt], DD, wmma::mem_row_major);
        }
}

// =================================================================================
extern "C" void kernel_launch(void* const* d_in, const int* in_sizes, int n_in,
                              void* d_out, int out_size)
{
    const float* inp    = (const float*)d_in[0];
    const float* W_logA = (const float*)d_in[1];
    const float* b_logA = (const float*)d_in[2];
    const float* W_XBC  = (const float*)d_in[3];
    const float* b_XBC  = (const float*)d_in[4];
    const float* W_gate = (const float*)d_in[5];
    const float* b_gate = (const float*)d_in[6];
    const float* W_out  = (const float*)d_in[7];
    const float* b_out  = (const float*)d_in[8];
    float* out = (float*)d_out;

    proj_kernel<<<dim3(32, 4, 16), 128>>>(inp, W_XBC, b_XBC, W_gate, b_gate, W_out);
    scan_kernel<<<32, 256>>>(inp, W_logA, b_logA);

    state_kernel<<<dim3(NCH-1, BHN), 256>>>();
    scan_state<<<dim3(BHN, 8), 256>>>();

    cudaFuncSetAttribute(attn_chunk, cudaFuncAttributeMaxDynamicSharedMemorySize, AC_SMEM);
    attn_chunk<<<dim3(NCH, BHN), 256, AC_SMEM>>>();

    cudaFuncSetAttribute(out_gemm_wmma, cudaFuncAttributeMaxDynamicSharedMemorySize, OG_SMEM);
    out_gemm_wmma<<<dim3(16, 8), 512, OG_SMEM>>>(b_out, out);
}

// round 15
// speedup vs baseline: 1.6214x; 1.0008x over previous
#include <cuda_runtime.h>
#include <cuda_bf16.h>
#include <mma.h>
#include <math.h>
#include <cstdint>

using namespace nvcuda;

#define BB 2
#define TT 1024
#define DD 1024
#define HH 16
#define CH 64
#define BHN (BB*HH)
#define NCH 16

// ---------------- device scratch ----------------
__device__ __align__(128) float g_cum [BHN*TT];
__device__ __align__(128) float g_gate[BHN*TT*CH];

// bf16 hi/lo activations (written directly by proj_kernel)
__device__ __align__(128) __nv_bfloat16 g_Xh[BHN*TT*CH];
__device__ __align__(128) __nv_bfloat16 g_Xl[BHN*TT*CH];
__device__ __align__(128) __nv_bfloat16 g_Bh[BHN*TT*CH];
__device__ __align__(128) __nv_bfloat16 g_Bl[BHN*TT*CH];
__device__ __align__(128) __nv_bfloat16 g_Chh[BHN*TT*CH];
__device__ __align__(128) __nv_bfloat16 g_Cll[BHN*TT*CH];

// chunked-scan intermediates
__device__ __align__(128) float         g_P  [BHN*NCH*64*64];
__device__ __align__(128) __nv_bfloat16 g_Sth[BHN*NCH*64*64];
__device__ __align__(128) __nv_bfloat16 g_Stl[BHN*NCH*64*64];

// output GEMM operands
__device__ __align__(128) __nv_bfloat16 g_YgH[BB*TT*DD];
__device__ __align__(128) __nv_bfloat16 g_YgL[BB*TT*DD];
__device__ __align__(128) __nv_bfloat16 g_WH [DD*DD];
__device__ __align__(128) __nv_bfloat16 g_WL [DD*DD];

// ---------------- helpers ----------------
__device__ __forceinline__ uint32_t smem_u32(const void* p) {
    uint32_t a;
    asm("{ .reg .u64 t; cvta.to.shared.u64 t, %1; cvt.u32.u64 %0, t; }" : "=r"(a) : "l"(p));
    return a;
}
__device__ __forceinline__ void cp16(uint32_t dst, const void* src) {
    asm volatile("cp.async.cg.shared.global [%0], [%1], 16;" :: "r"(dst), "l"(src) : "memory");
}
#define CP_COMMIT() asm volatile("cp.async.commit_group;" ::: "memory")
#define CP_WAIT(n)  asm volatile("cp.async.wait_group %0;" :: "n"(n) : "memory")

// =================================================================================
// Kernel 1: fused per-head projections (fp32 FFMA) + folded W_out hi/lo cvt.
// =================================================================================
__global__ __launch_bounds__(128) void proj_kernel(
    const float* __restrict__ inp,
    const float* __restrict__ W_XBC,  const float* __restrict__ b_XBC,
    const float* __restrict__ W_gate, const float* __restrict__ b_gate,
    const float* __restrict__ W_out)
{
    __shared__ float As[64*68];
    __shared__ float Ws[64*68];

    const int h     = blockIdx.z;
    const int mbase = blockIdx.x * 64;
    const int obase = blockIdx.y * 64;
    const int tid   = threadIdx.x;

    // folded W_out cvt: one float4 per thread
    {
        const int bid = blockIdx.x + 32*blockIdx.y + 128*blockIdx.z;
        const int i   = bid * 128 + tid;
        float4 v = ((const float4*)W_out)[i];
        float x[4] = {v.x, v.y, v.z, v.w};
        __nv_bfloat16 hh[4], ll[4];
#pragma unroll
        for (int k = 0; k < 4; ++k) {
            hh[k] = __float2bfloat16_rn(x[k]);
            ll[k] = __float2bfloat16_rn(x[k] - __bfloat162float(hh[k]));
        }
        ((__nv_bfloat162*)g_WH)[i*2+0] = __halves2bfloat162(hh[0], hh[1]);
        ((__nv_bfloat162*)g_WH)[i*2+1] = __halves2bfloat162(hh[2], hh[3]);
        ((__nv_bfloat162*)g_WL)[i*2+0] = __halves2bfloat162(ll[0], ll[1]);
        ((__nv_bfloat162*)g_WL)[i*2+1] = __halves2bfloat162(ll[2], ll[3]);
    }

    for (int l4 = tid; l4 < 64*16; l4 += 128) {
        int r = l4 >> 4, c4 = l4 & 15;
        float4 v = *(const float4*)&inp[(size_t)(mbase + r) * DD + h*CH + c4*4];
        *(float4*)&As[r*68 + c4*4] = v;
    }
    for (int l4 = tid; l4 < 64*16; l4 += 128) {
        int r = l4 >> 4, c4 = l4 & 15;
        int o = obase + r;
        float4 v;
        if (o < 192) v = *(const float4*)&W_XBC[((size_t)(h*192) + o)*CH + c4*4];
        else         v = *(const float4*)&W_gate[((size_t)(h*CH) + (o-192))*CH + c4*4];
        *(float4*)&Ws[r*68 + c4*4] = v;
    }
    __syncthreads();

    const int ty = tid >> 4, tx = tid & 15;
    float acc[8][4];
#pragma unroll
    for (int i = 0; i < 8; ++i)
#pragma unroll
        for (int j = 0; j < 4; ++j) acc[i][j] = 0.f;

#pragma unroll
    for (int k4 = 0; k4 < 16; ++k4) {
        float4 a[8], b[4];
#pragma unroll
        for (int i = 0; i < 8; ++i) a[i] = *(float4*)&As[(ty + 8*i)*68 + k4*4];
#pragma unroll
        for (int j = 0; j < 4; ++j) b[j] = *(float4*)&Ws[(tx + 16*j)*68 + k4*4];
#pragma unroll
        for (int i = 0; i < 8; ++i)
#pragma unroll
            for (int j = 0; j < 4; ++j) {
                acc[i][j] += a[i].x*b[j].x;
                acc[i][j] += a[i].y*b[j].y;
                acc[i][j] += a[i].z*b[j].z;
                acc[i][j] += a[i].w*b[j].w;
            }
    }

#pragma unroll
    for (int i = 0; i < 8; ++i) {
#pragma unroll
        for (int j = 0; j < 4; ++j) {
            int o  = obase + tx + 16*j;
            int m  = mbase + ty + 8*i;
            int b_ = m >> 10;
            int t  = m & (TT-1);
            int bh = b_*HH + h;
            float v = acc[i][j];
            if (o < 192) {
                float z = v + b_XBC[h*192 + o];
                float s = z / (1.f + __expf(-z));
                __nv_bfloat16 hi = __float2bfloat16_rn(s);
                __nv_bfloat16 lo = __float2bfloat16_rn(s - __bfloat162float(hi));
                size_t idx;
                if (o < 64)       { idx = ((size_t)bh*TT + t)*CH + o;       g_Xh[idx]=hi; g_Xl[idx]=lo; }
                else if (o < 128) { idx = ((size_t)bh*TT + t)*CH + (o-64);  g_Bh[idx]=hi; g_Bl[idx]=lo; }
                else              { idx = ((size_t)bh*TT + t)*CH + (o-128); g_Chh[idx]=hi; g_Cll[idx]=lo; }
            } else {
                g_gate[((size_t)bh*TT + t)*CH + (o-192)] = v + b_gate[h*CH + (o-192)];
            }
        }
    }
}

// =================================================================================
// Kernel 2: fused logA GEMV + inclusive cumsum
// =================================================================================
__global__ __launch_bounds__(256) void scan_kernel(
    const float* __restrict__ inp,
    const float* __restrict__ W_logA, const float* __restrict__ b_logA)
{
    __shared__ float s_tot[256];
    __shared__ float w[64];
    const int bh  = blockIdx.x;
    const int b_  = bh >> 4, h = bh & 15;
    const int tid = threadIdx.x;

    if (tid < 64) w[tid] = W_logA[h*CH + tid];
    __syncthreads();
    const float bA = b_logA[h];

    float v[4];
#pragma unroll
    for (int j = 0; j < 4; ++j) {
        const int t = tid*4 + j;
        const float4* row = (const float4*)&inp[((size_t)b_*TT + t)*DD + h*CH];
        float dot = 0.f;
#pragma unroll
        for (int c4 = 0; c4 < 16; ++c4) {
            float4 x = row[c4];
            dot += x.x*w[c4*4+0] + x.y*w[c4*4+1] + x.z*w[c4*4+2] + x.w*w[c4*4+3];
        }
        v[j] = dot + bA;
    }

    float r0 = v[0], r1 = r0+v[1], r2 = r1+v[2], r3 = r2+v[3];
    float total = r3;
    s_tot[tid] = r3;

    for (int off = 1; off < 256; off <<= 1) {
        __syncthreads();
        float add = (tid >= off) ? s_tot[tid - off] : 0.f;
        __syncthreads();
        s_tot[tid] += add;
    }
    __syncthreads();
    float excl = s_tot[tid] - total;

    float* out = g_cum + bh*TT;
    out[tid*4+0] = excl + r0;
    out[tid*4+1] = excl + r1;
    out[tid*4+2] = excl + r2;
    out[tid*4+3] = excl + r3;
}

// =================================================================================
// Kernel 3a: chunk moments P_k = B'^T @ X (unchanged)
// =================================================================================
#define KC_LDS 72
__global__ __launch_bounds__(256) void state_kernel()
{
    __shared__ __nv_bfloat16 Bp_h[64*KC_LDS], Bp_l[64*KC_LDS];
    __shared__ __nv_bfloat16 Xh_s[64*KC_LDS], Xl_s[64*KC_LDS];
    __shared__ float sc[64];

    const int k   = blockIdx.x;
    const int bh  = blockIdx.y;
    const int tid = threadIdx.x;
    const int w = tid >> 5, mrow = w & 3, nh = w >> 2;

    const uint32_t xh_b = smem_u32(Xh_s), xl_b = smem_u32(Xl_s);
#pragma unroll
    for (int s = 0; s < 4; ++s) {
        int l = tid + s*256;
        int tile = l >> 9, ww = l & 511, r = ww >> 3, q = ww & 7;
        const __nv_bfloat16* g = (tile ? g_Xl : g_Xh) + ((size_t)bh*TT + k*64 + r)*CH + q*8;
        cp16((tile ? xl_b : xh_b) + (uint32_t)(r*144 + q*16), g);
    }
    CP_COMMIT();
    if (tid < 64)
        sc[tid] = __expf(g_cum[bh*TT + k*64 + 63] - g_cum[bh*TT + k*64 + tid]);
    __syncthreads();

#pragma unroll
    for (int q = 0; q < 16; ++q) {
        int idx = tid + q*256;
        int ii = idx >> 6, jj = idx & 63;
        size_t go = ((size_t)bh*TT + k*64 + ii)*CH + jj;
        float v = (__bfloat162float(g_Bh[go]) + __bfloat162float(g_Bl[go])) * sc[ii];
        __nv_bfloat16 h = __float2bfloat16_rn(v);
        Bp_h[ii*KC_LDS + jj] = h;
        Bp_l[ii*KC_LDS + jj] = __float2bfloat16_rn(v - __bfloat162float(h));
    }
    CP_WAIT(0);
    __syncthreads();

    wmma::fragment<wmma::accumulator,16,16,16,float> pacc[2];
#pragma unroll
    for (int t2 = 0; t2 < 2; ++t2) wmma::fill_fragment(pacc[t2], 0.f);
#pragma unroll
    for (int kk = 0; kk < 4; ++kk) {
        wmma::fragment<wmma::matrix_a,16,16,16,__nv_bfloat16,wmma::col_major> aH, aL;
        wmma::load_matrix_sync(aH, &Bp_h[(kk*16)*KC_LDS + mrow*16], KC_LDS);
        wmma::load_matrix_sync(aL, &Bp_l[(kk*16)*KC_LDS + mrow*16], KC_LDS);
#pragma unroll
        for (int t2 = 0; t2 < 2; ++t2) {
            const int nt = nh*2 + t2;
            wmma::fragment<wmma::matrix_b,16,16,16,__nv_bfloat16,wmma::row_major> bH, bL;
            wmma::load_matrix_sync(bH, &Xh_s[(kk*16)*KC_LDS + nt*16], KC_LDS);
            wmma::load_matrix_sync(bL, &Xl_s[(kk*16)*KC_LDS + nt*16], KC_LDS);
            wmma::mma_sync(pacc[t2], aH, bH, pacc[t2]);
            wmma::mma_sync(pacc[t2], aH, bL, pacc[t2]);
            wmma::mma_sync(pacc[t2], aL, bH, pacc[t2]);
        }
    }
#pragma unroll
    for (int t2 = 0; t2 < 2; ++t2) {
        float* dst = g_P + ((size_t)bh*NCH + k)*4096 + (mrow*16)*64 + (nh*2+t2)*16;
        wmma::store_matrix_sync(dst, pacc[t2], 64, wmma::mem_row_major);
    }
}

// =================================================================================
// Kernel 3b: state scan (prefetched, unchanged)
// =================================================================================
__global__ __launch_bounds__(256) void scan_state()
{
    __shared__ float d[16];
    const int bh  = blockIdx.x;
    const int eb  = blockIdx.y * 512;
    const int tid = threadIdx.x;
    const int base = eb + tid*2;

    if (tid < 15) {
        float Ek = g_cum[bh*TT + tid*64 + 63];
        float Ep = (tid > 0) ? g_cum[bh*TT + tid*64 - 1] : 0.f;
        d[tid] = __expf(Ek - Ep);
    }

    float2 P[15];
#pragma unroll
    for (int k = 0; k < 15; ++k)
        P[k] = *(const float2*)&g_P[((size_t)bh*NCH + k)*4096 + base];
    __syncthreads();

    float2 S = make_float2(0.f, 0.f);
#pragma unroll
    for (int k = 0; k < 16; ++k) {
        size_t so = ((size_t)bh*NCH + k)*4096 + base;
        __nv_bfloat16 hx = __float2bfloat16_rn(S.x);
        __nv_bfloat16 hy = __float2bfloat16_rn(S.y);
        *(__nv_bfloat162*)(g_Sth + so) = __halves2bfloat162(hx, hy);
        *(__nv_bfloat162*)(g_Stl + so) = __halves2bfloat162(
            __float2bfloat16_rn(S.x - __bfloat162float(hx)),
            __float2bfloat16_rn(S.y - __bfloat162float(hy)));
        if (k < 15) {
            S.x = d[k]*S.x + P[k].x;
            S.y = d[k]*S.y + P[k].y;
        }
    }
}

// =================================================================================
// Kernel 3c: per-chunk output (unchanged)
// =================================================================================
#define AC_TILE (64*KC_LDS*2)
#define AC_S32A (8*AC_TILE)
#define AC_S32B (AC_S32A + 64*68*4)
#define AC_SCI  (AC_S32B + 64*68*4)
#define AC_SMEM (AC_SCI + 2*64*4)

__global__ __launch_bounds__(256) void attn_chunk()
{
    extern __shared__ __align__(128) char sm[];
    const uint32_t sbase = smem_u32(sm);
    __nv_bfloat16* Ch  = (__nv_bfloat16*)(sm);
    __nv_bfloat16* Cl  = (__nv_bfloat16*)(sm + 1*AC_TILE);
    __nv_bfloat16* Bh  = (__nv_bfloat16*)(sm + 2*AC_TILE);
    __nv_bfloat16* Bl  = (__nv_bfloat16*)(sm + 3*AC_TILE);
    __nv_bfloat16* Xh  = (__nv_bfloat16*)(sm + 4*AC_TILE);
    __nv_bfloat16* Xl  = (__nv_bfloat16*)(sm + 5*AC_TILE);
    __nv_bfloat16* Sth = (__nv_bfloat16*)(sm + 6*AC_TILE);
    __nv_bfloat16* Stl = (__nv_bfloat16*)(sm + 7*AC_TILE);
    float* S32a = (float*)(sm + AC_S32A);
    float* S32b = (float*)(sm + AC_S32B);
    float* sCi  = (float*)(sm + AC_SCI);
    float* sCj  = sCi + 64;

    const int k   = blockIdx.x;
    const int bh  = blockIdx.y;
    const int tid = threadIdx.x;
    const int w = tid >> 5, mrow = w & 3, nh = w >> 2;

    {
        const __nv_bfloat16* act[6] = {g_Chh, g_Cll, g_Bh, g_Bl, g_Xh, g_Xl};
#pragma unroll
        for (int s = 0; s < 12; ++s) {
            int l = tid + s*256;
            int tile = l >> 9, ww = l & 511, r = ww >> 3, q = ww & 7;
            const __nv_bfloat16* g = act[tile] + ((size_t)bh*TT + k*64 + r)*CH + q*8;
            cp16(sbase + (uint32_t)(tile*AC_TILE + r*144 + q*16), g);
        }
#pragma unroll
        for (int s = 0; s < 4; ++s) {
            int l = tid + s*256;
            int tile = l >> 9, ww = l & 511, r = ww >> 3, q = ww & 7;
            const __nv_bfloat16* g = (tile ? g_Stl : g_Sth) + ((size_t)bh*NCH + k)*4096 + r*64 + q*8;
            cp16(sbase + (uint32_t)((6+tile)*AC_TILE + r*144 + q*16), g);
        }
        CP_COMMIT();
    }
    {
        const float bk = (k > 0) ? g_cum[bh*TT + k*64 - 1] : 0.f;
        if (tid < 64)  sCi[tid] = __expf(g_cum[bh*TT + k*64 + tid] - bk);
        else if (tid < 128) sCj[tid-64] = __expf(bk - g_cum[bh*TT + k*64 + (tid-64)]);
    }
    CP_WAIT(0);
    __syncthreads();

    wmma::fragment<wmma::accumulator,16,16,16,float> sacc[2];
#pragma unroll
    for (int t2 = 0; t2 < 2; ++t2) wmma::fill_fragment(sacc[t2], 0.f);
#pragma unroll
    for (int kk = 0; kk < 4; ++kk) {
        wmma::fragment<wmma::matrix_a,16,16,16,__nv_bfloat16,wmma::row_major> aH, aL;
        wmma::load_matrix_sync(aH, &Ch[(mrow*16)*KC_LDS + kk*16], KC_LDS);
        wmma::load_matrix_sync(aL, &Cl[(mrow*16)*KC_LDS + kk*16], KC_LDS);
#pragma unroll
        for (int t2 = 0; t2 < 2; ++t2) {
            const int nt = nh*2 + t2;
            wmma::fragment<wmma::matrix_b,16,16,16,__nv_bfloat16,wmma::col_major> bH, bL;
            wmma::load_matrix_sync(bH, &Bh[(nt*16)*KC_LDS + kk*16], KC_LDS);
            wmma::load_matrix_sync(bL, &Bl[(nt*16)*KC_LDS + kk*16], KC_LDS);
            wmma::mma_sync(sacc[t2], aH, bH, sacc[t2]);
            wmma::mma_sync(sacc[t2], aH, bL, sacc[t2]);
            wmma::mma_sync(sacc[t2], aL, bH, sacc[t2]);
        }
    }
#pragma unroll
    for (int t2 = 0; t2 < 2; ++t2)
        wmma::store_matrix_sync(&S32a[(mrow*16)*68 + (nh*2+t2)*16], sacc[t2], 68,
                                wmma::mem_row_major);
    __syncthreads();

#pragma unroll
    for (int q = 0; q < 16; ++q) {
        int idx = (tid & 31) + q*32;
        int ii = mrow*16 + (idx >> 5);
        int jj = nh*32 + (idx & 31);
        float v = S32a[ii*68 + jj] * sCi[ii] * sCj[jj];
        if (jj > ii) v = 0.f;
        __nv_bfloat16 h = __float2bfloat16_rn(v);
        Bh[ii*KC_LDS + jj] = h;
        Bl[ii*KC_LDS + jj] = __float2bfloat16_rn(v - __bfloat162float(h));
    }
    __syncthreads();

    wmma::fragment<wmma::accumulator,16,16,16,float> yacc[2], zacc[2];
#pragma unroll
    for (int t2 = 0; t2 < 2; ++t2) { wmma::fill_fragment(yacc[t2], 0.f); wmma::fill_fragment(zacc[t2], 0.f); }
#pragma unroll
    for (int kk = 0; kk < 4; ++kk) {
        wmma::fragment<wmma::matrix_a,16,16,16,__nv_bfloat16,wmma::row_major> aH, aL, cH, cL;
        wmma::load_matrix_sync(aH, &Bh[(mrow*16)*KC_LDS + kk*16], KC_LDS);
        wmma::load_matrix_sync(aL, &Bl[(mrow*16)*KC_LDS + kk*16], KC_LDS);
        wmma::load_matrix_sync(cH, &Ch[(mrow*16)*KC_LDS + kk*16], KC_LDS);
        wmma::load_matrix_sync(cL, &Cl[(mrow*16)*KC_LDS + kk*16], KC_LDS);
#pragma unroll
        for (int t2 = 0; t2 < 2; ++t2) {
            const int ct = nh*2 + t2;
            wmma::fragment<wmma::matrix_b,16,16,16,__nv_bfloat16,wmma::row_major> bH, bL, sH, sL;
            wmma::load_matrix_sync(bH, &Xh[(kk*16)*KC_LDS + ct*16], KC_LDS);
            wmma::load_matrix_sync(bL, &Xl[(kk*16)*KC_LDS + ct*16], KC_LDS);
            wmma::mma_sync(yacc[t2], aH, bH, yacc[t2]);
            wmma::mma_sync(yacc[t2], aH, bL, yacc[t2]);
            wmma::mma_sync(yacc[t2], aL, bH, yacc[t2]);
            wmma::load_matrix_sync(sH, &Sth[(kk*16)*KC_LDS + ct*16], KC_LDS);
            wmma::load_matrix_sync(sL, &Stl[(kk*16)*KC_LDS + ct*16], KC_LDS);
            wmma::mma_sync(zacc[t2], cH, sH, zacc[t2]);
            wmma::mma_sync(zacc[t2], cH, sL, zacc[t2]);
            wmma::mma_sync(zacc[t2], cL, sH, zacc[t2]);
        }
    }
#pragma unroll
    for (int t2 = 0; t2 < 2; ++t2) {
        wmma::store_matrix_sync(&S32a[(mrow*16)*68 + (nh*2+t2)*16], yacc[t2], 68, wmma::mem_row_major);
        wmma::store_matrix_sync(&S32b[(mrow*16)*68 + (nh*2+t2)*16], zacc[t2], 68, wmma::mem_row_major);
    }
    __syncwarp();

    const int b_ = bh >> 4, h = bh & 15;
#pragma unroll
    for (int q = 0; q < 16; ++q) {
        int idx = (tid & 31) + q*32;
        int ii = mrow*16 + (idx >> 5);
        int cc = nh*32 + (idx & 31);
        float y = S32a[ii*68 + cc] + sCi[ii] * S32b[ii*68 + cc];
        float v = y * g_gate[((size_t)bh*TT + k*64 + ii)*CH + cc];
        size_t o = ((size_t)b_*TT + k*64 + ii)*DD + h*CH + cc;
        __nv_bfloat16 hh = __float2bfloat16_rn(v);
        g_YgH[o] = hh;
        g_YgL[o] = __float2bfloat16_rn(v - __bfloat162float(hh));
    }
}

// =================================================================================
// out_gemm_wmma: CTA tile 128(M) x 64(N), grid 16x16 = 256 CTAs, 256 threads.
// smem 64KB -> 3 CTAs/SM co-resident (cross-CTA latency hiding).
// 8 warps: warpM = wid&3 (32 rows), warpN = wid>>2 (2 n-groups of 32 cols).
// 2-stage cp.async double buffer, K-chunk 32.
// =================================================================================
#define NCHUNK   32
#define TA_B     10240                 // 128 rows * 80B (A tiles)
#define TB_B     5120                  // 64 rows * 80B (B tiles)
#define STAGE_B  (2*TA_B + 2*TB_B)     // 30720
#define BIAS_OFF (2*STAGE_B)           // 61440
#define OG_SMEM  (BIAS_OFF + 16*64*4)  // 65536

__global__ __launch_bounds__(256) void out_gemm_wmma(
    const float* __restrict__ b_out, float* __restrict__ out)
{
    extern __shared__ __align__(128) char smem[];
    const uint32_t sbase = smem_u32(smem);
    __nv_bfloat16* s_bf = (__nv_bfloat16*)smem;
    float* bias_s = (float*)(smem + BIAS_OFF);

    const int tid  = threadIdx.x;
    const int wid  = tid >> 5;
    const int warpM = wid & 3;        // 4 m-groups of 32 rows
    const int warpN = wid >> 2;       // 2 n-groups of 32 cols
    const int mb = blockIdx.x * 128;
    const int nb = blockIdx.y * 64;

    auto issue_stage = [&](int chunk, int p) {
        const int kc = chunk * 32;
        const uint32_t sb = sbase + (uint32_t)p * STAGE_B;
#pragma unroll
        for (int s = 0; s < 6; ++s) {
            const int l = tid + s * 256;          // < 1536
            const __nv_bfloat16* src;
            uint32_t dst;
            if (l < 512)        { int r = l >> 2, q = l & 3;
                src = g_YgH + (size_t)(mb + r) * DD + kc + q * 8;
                dst = sb + r * 80 + q * 16; }
            else if (l < 1024)  { int r = (l - 512) >> 2, q = l & 3;
                src = g_YgL + (size_t)(mb + r) * DD + kc + q * 8;
                dst = sb + TA_B + r * 80 + q * 16; }
            else if (l < 1280)  { int r = (l - 1024) >> 2, q = l & 3;
                src = g_WH + (size_t)(nb + r) * DD + kc + q * 8;
                dst = sb + 2*TA_B + r * 80 + q * 16; }
            else                { int r = (l - 1280) >> 2, q = l & 3;
                src = g_WL + (size_t)(nb + r) * DD + kc + q * 8;
                dst = sb + 2*TA_B + TB_B + r * 80 + q * 16; }
            cp16(dst, src);
        }
        CP_COMMIT();
    };

    issue_stage(0, 0);

    for (int i = tid; i < 16*64; i += 256) bias_s[i] = b_out[nb + (i & 63)];
    __syncthreads();

    wmma::fragment<wmma::accumulator, 16, 16, 16, float> acc[2][2];
#pragma unroll
    for (int mt = 0; mt < 2; ++mt)
#pragma unroll
        for (int nt = 0; nt < 2; ++nt)
            wmma::load_matrix_sync(acc[mt][nt], &bias_s[warpN*32 + nt*16], 64,
                                   wmma::mem_row_major);

    for (int c = 0; c < NCHUNK; ++c) {
        const int p = c & 1;
        if (c + 1 < NCHUNK) { issue_stage(c + 1, p ^ 1); CP_WAIT(1); }
        else                { CP_WAIT(0); }
        __syncthreads();

        __nv_bfloat16* sAH = s_bf + (size_t)p * (STAGE_B/2);
        __nv_bfloat16* sAL = sAH + TA_B/2;
        __nv_bfloat16* sBH = sAH + TA_B;
        __nv_bfloat16* sBL = sAH + TA_B + TB_B/2;

#pragma unroll
        for (int ks = 0; ks < 2; ++ks) {
            wmma::fragment<wmma::matrix_a, 16, 16, 16, __nv_bfloat16, wmma::row_major> aH[2], aL[2];
#pragma unroll
            for (int mt = 0; mt < 2; ++mt) {
                wmma::load_matrix_sync(aH[mt], &sAH[(warpM*32 + mt*16)*40 + ks*16], 40);
                wmma::load_matrix_sync(aL[mt], &sAL[(warpM*32 + mt*16)*40 + ks*16], 40);
            }
#pragma unroll
            for (int nt = 0; nt < 2; ++nt) {
                wmma::fragment<wmma::matrix_b, 16, 16, 16, __nv_bfloat16, wmma::col_major> bH, bL;
                wmma::load_matrix_sync(bH, &sBH[(warpN*32 + nt*16)*40 + ks*16], 40);
                wmma::load_matrix_sync(bL, &sBL[(warpN*32 + nt*16)*40 + ks*16], 40);
#pragma unroll
                for (int mt = 0; mt < 2; ++mt) {
                    wmma::mma_sync(acc[mt][nt], aH[mt], bH, acc[mt][nt]);
                    wmma::mma_sync(acc[mt][nt], aH[mt], bL, acc[mt][nt]);
                    wmma::mma_sync(acc[mt][nt], aL[mt], bH, acc[mt][nt]);
                }
            }
        }
        __syncthreads();
    }

#pragma unroll
    for (int mt = 0; mt < 2; ++mt)
#pragma unroll
        for (int nt = 0; nt < 2; ++nt) {
            float* dst = out + (size_t)(mb + warpM*32 + mt*16) * DD + nb + warpN*32 + nt*16;
            wmma::store_matrix_sync(dst, acc[mt][nt], DD, wmma::mem_row_major);
        }
}

// =================================================================================
extern "C" void kernel_launch(void* const* d_in, const int* in_sizes, int n_in,
                              void* d_out, int out_size)
{
    const float* inp    = (const float*)d_in[0];
    const float* W_logA = (const float*)d_in[1];
    const float* b_logA = (const float*)d_in[2];
    const float* W_XBC  = (const float*)d_in[3];
    const float* b_XBC  = (const float*)d_in[4];
    const float* W_gate = (const float*)d_in[5];
    const float* b_gate = (const float*)d_in[6];
    const float* W_out  = (const float*)d_in[7];
    const float* b_out  = (const float*)d_in[8];
    float* out = (float*)d_out;

    proj_kernel<<<dim3(32, 4, 16), 128>>>(inp, W_XBC, b_XBC, W_gate, b_gate, W_out);
    scan_kernel<<<32, 256>>>(inp, W_logA, b_logA);

    state_kernel<<<dim3(NCH-1, BHN), 256>>>();
    scan_state<<<dim3(BHN, 8), 256>>>();

    cudaFuncSetAttribute(attn_chunk, cudaFuncAttributeMaxDynamicSharedMemorySize, AC_SMEM);
    attn_chunk<<<dim3(NCH, BHN), 256, AC_SMEM>>>();

    cudaFuncSetAttribute(out_gemm_wmma, cudaFuncAttributeMaxDynamicSharedMemorySize, OG_SMEM);
    out_gemm_wmma<<<dim3(16, 16), 256, OG_SMEM>>>(b_out, out);
}

// round 16
// speedup vs baseline: 1.9812x; 1.2219x over previous
#include <cuda_runtime.h>
#include <cuda_bf16.h>
#include <mma.h>
#include <math.h>
#include <cstdint>

using namespace nvcuda;

#define BB 2
#define TT 1024
#define DD 1024
#define HH 16
#define CH 64
#define BHN (BB*HH)
#define NCH 16

// ---------------- device scratch ----------------
__device__ __align__(128) float g_cum [BHN*TT];
__device__ __align__(128) float g_gate[BHN*TT*CH];

// hi/lo splits of inputs and packed projection weights
__device__ __align__(128) __nv_bfloat16 g_Ih [BB*TT*DD];
__device__ __align__(128) __nv_bfloat16 g_Il [BB*TT*DD];
__device__ __align__(128) __nv_bfloat16 g_Wph[HH*256*CH];   // rows 0-191 XBC, 192-255 gate
__device__ __align__(128) __nv_bfloat16 g_Wpl[HH*256*CH];

// bf16 hi/lo activations
__device__ __align__(128) __nv_bfloat16 g_Xh[BHN*TT*CH];
__device__ __align__(128) __nv_bfloat16 g_Xl[BHN*TT*CH];
__device__ __align__(128) __nv_bfloat16 g_Bh[BHN*TT*CH];
__device__ __align__(128) __nv_bfloat16 g_Bl[BHN*TT*CH];
__device__ __align__(128) __nv_bfloat16 g_Chh[BHN*TT*CH];
__device__ __align__(128) __nv_bfloat16 g_Cll[BHN*TT*CH];

// chunked-scan intermediates
__device__ __align__(128) float         g_P  [BHN*NCH*64*64];
__device__ __align__(128) __nv_bfloat16 g_Sth[BHN*NCH*64*64];
__device__ __align__(128) __nv_bfloat16 g_Stl[BHN*NCH*64*64];

// output GEMM operands
__device__ __align__(128) __nv_bfloat16 g_YgH[BB*TT*DD];
__device__ __align__(128) __nv_bfloat16 g_YgL[BB*TT*DD];
__device__ __align__(128) __nv_bfloat16 g_WH [DD*DD];
__device__ __align__(128) __nv_bfloat16 g_WL [DD*DD];

// ---------------- helpers ----------------
__device__ __forceinline__ uint32_t smem_u32(const void* p) {
    uint32_t a;
    asm("{ .reg .u64 t; cvta.to.shared.u64 t, %1; cvt.u32.u64 %0, t; }" : "=r"(a) : "l"(p));
    return a;
}
__device__ __forceinline__ void cp16(uint32_t dst, const void* src) {
    asm volatile("cp.async.cg.shared.global [%0], [%1], 16;" :: "r"(dst), "l"(src) : "memory");
}
#define CP_COMMIT() asm volatile("cp.async.commit_group;" ::: "memory")
#define CP_WAIT(n)  asm volatile("cp.async.wait_group %0;" :: "n"(n) : "memory")

// =================================================================================
// Kernel 0: all fp32 -> bf16 hi/lo conversions: inp (524288 f4), packed proj
// weights (65536 f4), W_out (262144 f4). Grid 3328 x 256.
// =================================================================================
__global__ __launch_bounds__(256) void cvt_all(
    const float* __restrict__ inp,  const float* __restrict__ W_XBC,
    const float* __restrict__ W_gate, const float* __restrict__ W_out)
{
    const int i = blockIdx.x * 256 + threadIdx.x;
    float4 v;
    __nv_bfloat16 *dh, *dl;
    int base;
    if (i < 524288) {
        v = ((const float4*)inp)[i];
        dh = g_Ih; dl = g_Il; base = i;
    } else if (i < 524288 + 65536) {
        const int j = i - 524288;
        const int e = j * 4;
        const int hh = e >> 14;             // / (256*64)
        const int rem = e & 16383;
        const int o = rem >> 6, c = rem & 63;
        const float* s = (o < 192) ? &W_XBC[((size_t)hh*192 + o)*CH + c]
                                   : &W_gate[((size_t)hh*CH + (o-192))*CH + c];
        v = *(const float4*)s;
        dh = g_Wph; dl = g_Wpl; base = j;
    } else {
        base = i - 524288 - 65536;
        v = ((const float4*)W_out)[base];
        dh = g_WH; dl = g_WL;
    }
    float x[4] = {v.x, v.y, v.z, v.w};
    __nv_bfloat16 h[4], l[4];
#pragma unroll
    for (int k = 0; k < 4; ++k) {
        h[k] = __float2bfloat16_rn(x[k]);
        l[k] = __float2bfloat16_rn(x[k] - __bfloat162float(h[k]));
    }
    ((__nv_bfloat162*)dh)[base*2+0] = __halves2bfloat162(h[0], h[1]);
    ((__nv_bfloat162*)dh)[base*2+1] = __halves2bfloat162(h[2], h[3]);
    ((__nv_bfloat162*)dl)[base*2+0] = __halves2bfloat162(l[0], l[1]);
    ((__nv_bfloat162*)dl)[base*2+1] = __halves2bfloat162(l[2], l[3]);
}

// =================================================================================
// Kernel 1: proj via wmma bf16x3. Grid (16 m-tiles, 4 segments, 16 heads), 256 thr.
// CTA tile 128(m) x 64(o), K=64 one-shot. seg: 0=X 1=B 2=C (silu+split), 3=gate.
// smem 55KB -> 4 CTA/SM; acc 2x2 frags; branch-free contiguous epilogue.
// =================================================================================
#define PM_XT   18432                  // 128*144
#define PM_WT   9216                   // 64*144
#define PM_SMEM (2*PM_XT + 2*PM_WT)    // 55296

__global__ __launch_bounds__(256) void proj_mma(
    const float* __restrict__ b_XBC, const float* __restrict__ b_gate)
{
    extern __shared__ __align__(128) char sm[];
    const uint32_t sbase = smem_u32(sm);
    __nv_bfloat16* Xh_s = (__nv_bfloat16*)sm;
    __nv_bfloat16* Xl_s = (__nv_bfloat16*)(sm + PM_XT);
    __nv_bfloat16* Wh_s = (__nv_bfloat16*)(sm + 2*PM_XT);
    __nv_bfloat16* Wl_s = (__nv_bfloat16*)(sm + 2*PM_XT + PM_WT);
    float* S32 = (float*)sm;   // overlays X tiles after MMA (34816 <= 36864)

    const int mb  = blockIdx.x * 128;
    const int seg = blockIdx.y;
    const int h   = blockIdx.z;
    const int tid = threadIdx.x;
    const int wid = tid >> 5, warpM = wid & 3, warpN = wid >> 2;

    // X tiles (hi/lo): 2 x 128 rows x 8 x 16B
#pragma unroll
    for (int s = 0; s < 8; ++s) {
        int l = tid + s*256;
        int tile = l >> 10, ww = l & 1023, r = ww >> 3, q = ww & 7;
        const __nv_bfloat16* g = (tile ? g_Il : g_Ih) + (size_t)(mb + r)*DD + h*CH + q*8;
        cp16(sbase + (uint32_t)(tile*PM_XT + r*144 + q*16), g);
    }
    // W tiles (hi/lo): 2 x 64 rows x 8 x 16B
#pragma unroll
    for (int s = 0; s < 4; ++s) {
        int l = tid + s*256;
        int tile = l >> 9, ww = l & 511, r = ww >> 3, q = ww & 7;
        const __nv_bfloat16* g = (tile ? g_Wpl : g_Wph) + ((size_t)h*256 + seg*64 + r)*CH + q*8;
        cp16(sbase + (uint32_t)(2*PM_XT + tile*PM_WT + r*144 + q*16), g);
    }
    CP_COMMIT();
    CP_WAIT(0);
    __syncthreads();

    wmma::fragment<wmma::accumulator,16,16,16,float> acc[2][2];
#pragma unroll
    for (int mt = 0; mt < 2; ++mt)
#pragma unroll
        for (int nt = 0; nt < 2; ++nt) wmma::fill_fragment(acc[mt][nt], 0.f);

#pragma unroll
    for (int kk = 0; kk < 4; ++kk) {
        wmma::fragment<wmma::matrix_a,16,16,16,__nv_bfloat16,wmma::row_major> aH[2], aL[2];
#pragma unroll
        for (int mt = 0; mt < 2; ++mt) {
            wmma::load_matrix_sync(aH[mt], &Xh_s[(warpM*32 + mt*16)*72 + kk*16], 72);
            wmma::load_matrix_sync(aL[mt], &Xl_s[(warpM*32 + mt*16)*72 + kk*16], 72);
        }
#pragma unroll
        for (int nt = 0; nt < 2; ++nt) {
            wmma::fragment<wmma::matrix_b,16,16,16,__nv_bfloat16,wmma::col_major> bH, bL;
            wmma::load_matrix_sync(bH, &Wh_s[(warpN*32 + nt*16)*72 + kk*16], 72);
            wmma::load_matrix_sync(bL, &Wl_s[(warpN*32 + nt*16)*72 + kk*16], 72);
#pragma unroll
            for (int mt = 0; mt < 2; ++mt) {
                wmma::mma_sync(acc[mt][nt], aH[mt], bH, acc[mt][nt]);
                wmma::mma_sync(acc[mt][nt], aH[mt], bL, acc[mt][nt]);
                wmma::mma_sync(acc[mt][nt], aL[mt], bH, acc[mt][nt]);
            }
        }
    }
    __syncthreads();   // all warps done reading X tiles -> S32 overlay safe

#pragma unroll
    for (int mt = 0; mt < 2; ++mt)
#pragma unroll
        for (int nt = 0; nt < 2; ++nt)
            wmma::store_matrix_sync(&S32[(warpM*32 + mt*16)*68 + warpN*32 + nt*16],
                                    acc[mt][nt], 68, wmma::mem_row_major);
    __syncthreads();

    // epilogue: thread -> (row = tid>>1, 32-col half). Branch-free per segment.
    const int row = tid >> 1;
    const int cb  = (tid & 1) * 32;
    const int m   = mb + row;
    const int b_  = m >> 10;
    const int t   = m & (TT-1);
    const int bh  = b_*HH + h;
    const size_t o0 = ((size_t)bh*TT + t)*CH;

    if (seg < 3) {
        const float* bias = b_XBC + h*192 + seg*64;
        __nv_bfloat16 *dh, *dl;
        if (seg == 0)      { dh = g_Xh;  dl = g_Xl;  }
        else if (seg == 1) { dh = g_Bh;  dl = g_Bl;  }
        else               { dh = g_Chh; dl = g_Cll; }
#pragma unroll
        for (int i = 0; i < 32; i += 2) {
            const int c0 = cb + i;
            float z0 = S32[row*68 + c0]     + bias[c0];
            float z1 = S32[row*68 + c0 + 1] + bias[c0 + 1];
            float s0 = z0 / (1.f + __expf(-z0));
            float s1 = z1 / (1.f + __expf(-z1));
            __nv_bfloat16 h0 = __float2bfloat16_rn(s0);
            __nv_bfloat16 h1 = __float2bfloat16_rn(s1);
            *(__nv_bfloat162*)(dh + o0 + c0) = __halves2bfloat162(h0, h1);
            *(__nv_bfloat162*)(dl + o0 + c0) = __halves2bfloat162(
                __float2bfloat16_rn(s0 - __bfloat162float(h0)),
                __float2bfloat16_rn(s1 - __bfloat162float(h1)));
        }
    } else {
        const float* bias = b_gate + h*CH;
#pragma unroll
        for (int i = 0; i < 32; i += 4) {
            const int c0 = cb + i;
            float4 v;
            v.x = S32[row*68 + c0 + 0] + bias[c0 + 0];
            v.y = S32[row*68 + c0 + 1] + bias[c0 + 1];
            v.z = S32[row*68 + c0 + 2] + bias[c0 + 2];
            v.w = S32[row*68 + c0 + 3] + bias[c0 + 3];
            *(float4*)&g_gate[o0 + c0] = v;
        }
    }
}

// =================================================================================
// Kernel 2: fused logA GEMV + inclusive cumsum (unchanged, reads fp32 inp)
// =================================================================================
__global__ __launch_bounds__(256) void scan_kernel(
    const float* __restrict__ inp,
    const float* __restrict__ W_logA, const float* __restrict__ b_logA)
{
    __shared__ float s_tot[256];
    __shared__ float w[64];
    const int bh  = blockIdx.x;
    const int b_  = bh >> 4, h = bh & 15;
    const int tid = threadIdx.x;

    if (tid < 64) w[tid] = W_logA[h*CH + tid];
    __syncthreads();
    const float bA = b_logA[h];

    float v[4];
#pragma unroll
    for (int j = 0; j < 4; ++j) {
        const int t = tid*4 + j;
        const float4* row = (const float4*)&inp[((size_t)b_*TT + t)*DD + h*CH];
        float dot = 0.f;
#pragma unroll
        for (int c4 = 0; c4 < 16; ++c4) {
            float4 x = row[c4];
            dot += x.x*w[c4*4+0] + x.y*w[c4*4+1] + x.z*w[c4*4+2] + x.w*w[c4*4+3];
        }
        v[j] = dot + bA;
    }

    float r0 = v[0], r1 = r0+v[1], r2 = r1+v[2], r3 = r2+v[3];
    float total = r3;
    s_tot[tid] = r3;

    for (int off = 1; off < 256; off <<= 1) {
        __syncthreads();
        float add = (tid >= off) ? s_tot[tid - off] : 0.f;
        __syncthreads();
        s_tot[tid] += add;
    }
    __syncthreads();
    float excl = s_tot[tid] - total;

    float* out = g_cum + bh*TT;
    out[tid*4+0] = excl + r0;
    out[tid*4+1] = excl + r1;
    out[tid*4+2] = excl + r2;
    out[tid*4+3] = excl + r3;
}

// =================================================================================
// Kernel 3a: chunk moments P_k = B'^T @ X (unchanged)
// =================================================================================
#define KC_LDS 72
__global__ __launch_bounds__(256) void state_kernel()
{
    __shared__ __nv_bfloat16 Bp_h[64*KC_LDS], Bp_l[64*KC_LDS];
    __shared__ __nv_bfloat16 Xh_s[64*KC_LDS], Xl_s[64*KC_LDS];
    __shared__ float sc[64];

    const int k   = blockIdx.x;
    const int bh  = blockIdx.y;
    const int tid = threadIdx.x;
    const int w = tid >> 5, mrow = w & 3, nh = w >> 2;

    const uint32_t xh_b = smem_u32(Xh_s), xl_b = smem_u32(Xl_s);
#pragma unroll
    for (int s = 0; s < 4; ++s) {
        int l = tid + s*256;
        int tile = l >> 9, ww = l & 511, r = ww >> 3, q = ww & 7;
        const __nv_bfloat16* g = (tile ? g_Xl : g_Xh) + ((size_t)bh*TT + k*64 + r)*CH + q*8;
        cp16((tile ? xl_b : xh_b) + (uint32_t)(r*144 + q*16), g);
    }
    CP_COMMIT();
    if (tid < 64)
        sc[tid] = __expf(g_cum[bh*TT + k*64 + 63] - g_cum[bh*TT + k*64 + tid]);
    __syncthreads();

#pragma unroll
    for (int q = 0; q < 16; ++q) {
        int idx = tid + q*256;
        int ii = idx >> 6, jj = idx & 63;
        size_t go = ((size_t)bh*TT + k*64 + ii)*CH + jj;
        float v = (__bfloat162float(g_Bh[go]) + __bfloat162float(g_Bl[go])) * sc[ii];
        __nv_bfloat16 h = __float2bfloat16_rn(v);
        Bp_h[ii*KC_LDS + jj] = h;
        Bp_l[ii*KC_LDS + jj] = __float2bfloat16_rn(v - __bfloat162float(h));
    }
    CP_WAIT(0);
    __syncthreads();

    wmma::fragment<wmma::accumulator,16,16,16,float> pacc[2];
#pragma unroll
    for (int t2 = 0; t2 < 2; ++t2) wmma::fill_fragment(pacc[t2], 0.f);
#pragma unroll
    for (int kk = 0; kk < 4; ++kk) {
        wmma::fragment<wmma::matrix_a,16,16,16,__nv_bfloat16,wmma::col_major> aH, aL;
        wmma::load_matrix_sync(aH, &Bp_h[(kk*16)*KC_LDS + mrow*16], KC_LDS);
        wmma::load_matrix_sync(aL, &Bp_l[(kk*16)*KC_LDS + mrow*16], KC_LDS);
#pragma unroll
        for (int t2 = 0; t2 < 2; ++t2) {
            const int nt = nh*2 + t2;
            wmma::fragment<wmma::matrix_b,16,16,16,__nv_bfloat16,wmma::row_major> bH, bL;
            wmma::load_matrix_sync(bH, &Xh_s[(kk*16)*KC_LDS + nt*16], KC_LDS);
            wmma::load_matrix_sync(bL, &Xl_s[(kk*16)*KC_LDS + nt*16], KC_LDS);
            wmma::mma_sync(pacc[t2], aH, bH, pacc[t2]);
            wmma::mma_sync(pacc[t2], aH, bL, pacc[t2]);
            wmma::mma_sync(pacc[t2], aL, bH, pacc[t2]);
        }
    }
#pragma unroll
    for (int t2 = 0; t2 < 2; ++t2) {
        float* dst = g_P + ((size_t)bh*NCH + k)*4096 + (mrow*16)*64 + (nh*2+t2)*16;
        wmma::store_matrix_sync(dst, pacc[t2], 64, wmma::mem_row_major);
    }
}

// =================================================================================
// Kernel 3b: state scan (prefetched, unchanged)
// =================================================================================
__global__ __launch_bounds__(256) void scan_state()
{
    __shared__ float d[16];
    const int bh  = blockIdx.x;
    const int eb  = blockIdx.y * 512;
    const int tid = threadIdx.x;
    const int base = eb + tid*2;

    if (tid < 15) {
        float Ek = g_cum[bh*TT + tid*64 + 63];
        float Ep = (tid > 0) ? g_cum[bh*TT + tid*64 - 1] : 0.f;
        d[tid] = __expf(Ek - Ep);
    }

    float2 P[15];
#pragma unroll
    for (int k = 0; k < 15; ++k)
        P[k] = *(const float2*)&g_P[((size_t)bh*NCH + k)*4096 + base];
    __syncthreads();

    float2 S = make_float2(0.f, 0.f);
#pragma unroll
    for (int k = 0; k < 16; ++k) {
        size_t so = ((size_t)bh*NCH + k)*4096 + base;
        __nv_bfloat16 hx = __float2bfloat16_rn(S.x);
        __nv_bfloat16 hy = __float2bfloat16_rn(S.y);
        *(__nv_bfloat162*)(g_Sth + so) = __halves2bfloat162(hx, hy);
        *(__nv_bfloat162*)(g_Stl + so) = __halves2bfloat162(
            __float2bfloat16_rn(S.x - __bfloat162float(hx)),
            __float2bfloat16_rn(S.y - __bfloat162float(hy)));
        if (k < 15) {
            S.x = d[k]*S.x + P[k].x;
            S.y = d[k]*S.y + P[k].y;
        }
    }
}

// =================================================================================
// Kernel 3c: per-chunk output (unchanged)
// =================================================================================
#define AC_TILE (64*KC_LDS*2)
#define AC_S32A (8*AC_TILE)
#define AC_S32B (AC_S32A + 64*68*4)
#define AC_SCI  (AC_S32B + 64*68*4)
#define AC_SMEM (AC_SCI + 2*64*4)

__global__ __launch_bounds__(256) void attn_chunk()
{
    extern __shared__ __align__(128) char sm[];
    const uint32_t sbase = smem_u32(sm);
    __nv_bfloat16* Ch  = (__nv_bfloat16*)(sm);
    __nv_bfloat16* Cl  = (__nv_bfloat16*)(sm + 1*AC_TILE);
    __nv_bfloat16* Bh  = (__nv_bfloat16*)(sm + 2*AC_TILE);
    __nv_bfloat16* Bl  = (__nv_bfloat16*)(sm + 3*AC_TILE);
    __nv_bfloat16* Xh  = (__nv_bfloat16*)(sm + 4*AC_TILE);
    __nv_bfloat16* Xl  = (__nv_bfloat16*)(sm + 5*AC_TILE);
    __nv_bfloat16* Sth = (__nv_bfloat16*)(sm + 6*AC_TILE);
    __nv_bfloat16* Stl = (__nv_bfloat16*)(sm + 7*AC_TILE);
    float* S32a = (float*)(sm + AC_S32A);
    float* S32b = (float*)(sm + AC_S32B);
    float* sCi  = (float*)(sm + AC_SCI);
    float* sCj  = sCi + 64;

    const int k   = blockIdx.x;
    const int bh  = blockIdx.y;
    const int tid = threadIdx.x;
    const int w = tid >> 5, mrow = w & 3, nh = w >> 2;

    {
        const __nv_bfloat16* act[6] = {g_Chh, g_Cll, g_Bh, g_Bl, g_Xh, g_Xl};
#pragma unroll
        for (int s = 0; s < 12; ++s) {
            int l = tid + s*256;
            int tile = l >> 9, ww = l & 511, r = ww >> 3, q = ww & 7;
            const __nv_bfloat16* g = act[tile] + ((size_t)bh*TT + k*64 + r)*CH + q*8;
            cp16(sbase + (uint32_t)(tile*AC_TILE + r*144 + q*16), g);
        }
#pragma unroll
        for (int s = 0; s < 4; ++s) {
            int l = tid + s*256;
            int tile = l >> 9, ww = l & 511, r = ww >> 3, q = ww & 7;
            const __nv_bfloat16* g = (tile ? g_Stl : g_Sth) + ((size_t)bh*NCH + k)*4096 + r*64 + q*8;
            cp16(sbase + (uint32_t)((6+tile)*AC_TILE + r*144 + q*16), g);
        }
        CP_COMMIT();
    }
    {
        const float bk = (k > 0) ? g_cum[bh*TT + k*64 - 1] : 0.f;
        if (tid < 64)  sCi[tid] = __expf(g_cum[bh*TT + k*64 + tid] - bk);
        else if (tid < 128) sCj[tid-64] = __expf(bk - g_cum[bh*TT + k*64 + (tid-64)]);
    }
    CP_WAIT(0);
    __syncthreads();

    wmma::fragment<wmma::accumulator,16,16,16,float> sacc[2];
#pragma unroll
    for (int t2 = 0; t2 < 2; ++t2) wmma::fill_fragment(sacc[t2], 0.f);
#pragma unroll
    for (int kk = 0; kk < 4; ++kk) {
        wmma::fragment<wmma::matrix_a,16,16,16,__nv_bfloat16,wmma::row_major> aH, aL;
        wmma::load_matrix_sync(aH, &Ch[(mrow*16)*KC_LDS + kk*16], KC_LDS);
        wmma::load_matrix_sync(aL, &Cl[(mrow*16)*KC_LDS + kk*16], KC_LDS);
#pragma unroll
        for (int t2 = 0; t2 < 2; ++t2) {
            const int nt = nh*2 + t2;
            wmma::fragment<wmma::matrix_b,16,16,16,__nv_bfloat16,wmma::col_major> bH, bL;
            wmma::load_matrix_sync(bH, &Bh[(nt*16)*KC_LDS + kk*16], KC_LDS);
            wmma::load_matrix_sync(bL, &Bl[(nt*16)*KC_LDS + kk*16], KC_LDS);
            wmma::mma_sync(sacc[t2], aH, bH, sacc[t2]);
            wmma::mma_sync(sacc[t2], aH, bL, sacc[t2]);
            wmma::mma_sync(sacc[t2], aL, bH, sacc[t2]);
        }
    }
#pragma unroll
    for (int t2 = 0; t2 < 2; ++t2)
        wmma::store_matrix_sync(&S32a[(mrow*16)*68 + (nh*2+t2)*16], sacc[t2], 68,
                                wmma::mem_row_major);
    __syncthreads();

#pragma unroll
    for (int q = 0; q < 16; ++q) {
        int idx = (tid & 31) + q*32;
        int ii = mrow*16 + (idx >> 5);
        int jj = nh*32 + (idx & 31);
        float v = S32a[ii*68 + jj] * sCi[ii] * sCj[jj];
        if (jj > ii) v = 0.f;
        __nv_bfloat16 h = __float2bfloat16_rn(v);
        Bh[ii*KC_LDS + jj] = h;
        Bl[ii*KC_LDS + jj] = __float2bfloat16_rn(v - __bfloat162float(h));
    }
    __syncthreads();

    wmma::fragment<wmma::accumulator,16,16,16,float> yacc[2], zacc[2];
#pragma unroll
    for (int t2 = 0; t2 < 2; ++t2) { wmma::fill_fragment(yacc[t2], 0.f); wmma::fill_fragment(zacc[t2], 0.f); }
#pragma unroll
    for (int kk = 0; kk < 4; ++kk) {
        wmma::fragment<wmma::matrix_a,16,16,16,__nv_bfloat16,wmma::row_major> aH, aL, cH, cL;
        wmma::load_matrix_sync(aH, &Bh[(mrow*16)*KC_LDS + kk*16], KC_LDS);
        wmma::load_matrix_sync(aL, &Bl[(mrow*16)*KC_LDS + kk*16], KC_LDS);
        wmma::load_matrix_sync(cH, &Ch[(mrow*16)*KC_LDS + kk*16], KC_LDS);
        wmma::load_matrix_sync(cL, &Cl[(mrow*16)*KC_LDS + kk*16], KC_LDS);
#pragma unroll
        for (int t2 = 0; t2 < 2; ++t2) {
            const int ct = nh*2 + t2;
            wmma::fragment<wmma::matrix_b,16,16,16,__nv_bfloat16,wmma::row_major> bH, bL, sH, sL;
            wmma::load_matrix_sync(bH, &Xh[(kk*16)*KC_LDS + ct*16], KC_LDS);
            wmma::load_matrix_sync(bL, &Xl[(kk*16)*KC_LDS + ct*16], KC_LDS);
            wmma::mma_sync(yacc[t2], aH, bH, yacc[t2]);
            wmma::mma_sync(yacc[t2], aH, bL, yacc[t2]);
            wmma::mma_sync(yacc[t2], aL, bH, yacc[t2]);
            wmma::load_matrix_sync(sH, &Sth[(kk*16)*KC_LDS + ct*16], KC_LDS);
            wmma::load_matrix_sync(sL, &Stl[(kk*16)*KC_LDS + ct*16], KC_LDS);
            wmma::mma_sync(zacc[t2], cH, sH, zacc[t2]);
            wmma::mma_sync(zacc[t2], cH, sL, zacc[t2]);
            wmma::mma_sync(zacc[t2], cL, sH, zacc[t2]);
        }
    }
#pragma unroll
    for (int t2 = 0; t2 < 2; ++t2) {
        wmma::store_matrix_sync(&S32a[(mrow*16)*68 + (nh*2+t2)*16], yacc[t2], 68, wmma::mem_row_major);
        wmma::store_matrix_sync(&S32b[(mrow*16)*68 + (nh*2+t2)*16], zacc[t2], 68, wmma::mem_row_major);
    }
    __syncwarp();

    const int b_ = bh >> 4, h = bh & 15;
#pragma unroll
    for (int q = 0; q < 16; ++q) {
        int idx = (tid & 31) + q*32;
        int ii = mrow*16 + (idx >> 5);
        int cc = nh*32 + (idx & 31);
        float y = S32a[ii*68 + cc] + sCi[ii] * S32b[ii*68 + cc];
        float v = y * g_gate[((size_t)bh*TT + k*64 + ii)*CH + cc];
        size_t o = ((size_t)b_*TT + k*64 + ii)*DD + h*CH + cc;
        __nv_bfloat16 hh = __float2bfloat16_rn(v);
        g_YgH[o] = hh;
        g_YgL[o] = __float2bfloat16_rn(v - __bfloat162float(hh));
    }
}

// =================================================================================
// out_gemm_wmma: CTA tile 128(M) x 64(N), grid 16x16, 256 threads (R15 version)
// =================================================================================
#define NCHUNK   32
#define TA_B     10240
#define TB_B     5120
#define STAGE_B  (2*TA_B + 2*TB_B)
#define BIAS_OFF (2*STAGE_B)
#define OG_SMEM  (BIAS_OFF + 16*64*4)

__global__ __launch_bounds__(256) void out_gemm_wmma(
    const float* __restrict__ b_out, float* __restrict__ out)
{
    extern __shared__ __align__(128) char smem[];
    const uint32_t sbase = smem_u32(smem);
    __nv_bfloat16* s_bf = (__nv_bfloat16*)smem;
    float* bias_s = (float*)(smem + BIAS_OFF);

    const int tid  = threadIdx.x;
    const int wid  = tid >> 5;
    const int warpM = wid & 3;
    const int warpN = wid >> 2;
    const int mb = blockIdx.x * 128;
    const int nb = blockIdx.y * 64;

    auto issue_stage = [&](int chunk, int p) {
        const int kc = chunk * 32;
        const uint32_t sb = sbase + (uint32_t)p * STAGE_B;
#pragma unroll
        for (int s = 0; s < 6; ++s) {
            const int l = tid + s * 256;
            const __nv_bfloat16* src;
            uint32_t dst;
            if (l < 512)        { int r = l >> 2, q = l & 3;
                src = g_YgH + (size_t)(mb + r) * DD + kc + q * 8;
                dst = sb + r * 80 + q * 16; }
            else if (l < 1024)  { int r = (l - 512) >> 2, q = l & 3;
                src = g_YgL + (size_t)(mb + r) * DD + kc + q * 8;
                dst = sb + TA_B + r * 80 + q * 16; }
            else if (l < 1280)  { int r = (l - 1024) >> 2, q = l & 3;
                src = g_WH + (size_t)(nb + r) * DD + kc + q * 8;
                dst = sb + 2*TA_B + r * 80 + q * 16; }
            else                { int r = (l - 1280) >> 2, q = l & 3;
                src = g_WL + (size_t)(nb + r) * DD + kc + q * 8;
                dst = sb + 2*TA_B + TB_B + r * 80 + q * 16; }
            cp16(dst, src);
        }
        CP_COMMIT();
    };

    issue_stage(0, 0);

    for (int i = tid; i < 16*64; i += 256) bias_s[i] = b_out[nb + (i & 63)];
    __syncthreads();

    wmma::fragment<wmma::accumulator, 16, 16, 16, float> acc[2][2];
#pragma unroll
    for (int mt = 0; mt < 2; ++mt)
#pragma unroll
        for (int nt = 0; nt < 2; ++nt)
            wmma::load_matrix_sync(acc[mt][nt], &bias_s[warpN*32 + nt*16], 64,
                                   wmma::mem_row_major);

    for (int c = 0; c < NCHUNK; ++c) {
        const int p = c & 1;
        if (c + 1 < NCHUNK) { issue_stage(c + 1, p ^ 1); CP_WAIT(1); }
        else                { CP_WAIT(0); }
        __syncthreads();

        __nv_bfloat16* sAH = s_bf + (size_t)p * (STAGE_B/2);
        __nv_bfloat16* sAL = sAH + TA_B/2;
        __nv_bfloat16* sBH = sAH + TA_B;
        __nv_bfloat16* sBL = sAH + TA_B + TB_B/2;

#pragma unroll
        for (int ks = 0; ks < 2; ++ks) {
            wmma::fragment<wmma::matrix_a, 16, 16, 16, __nv_bfloat16, wmma::row_major> aH[2], aL[2];
#pragma unroll
            for (int mt = 0; mt < 2; ++mt) {
                wmma::load_matrix_sync(aH[mt], &sAH[(warpM*32 + mt*16)*40 + ks*16], 40);
                wmma::load_matrix_sync(aL[mt], &sAL[(warpM*32 + mt*16)*40 + ks*16], 40);
            }
#pragma unroll
            for (int nt = 0; nt < 2; ++nt) {
                wmma::fragment<wmma::matrix_b, 16, 16, 16, __nv_bfloat16, wmma::col_major> bH, bL;
                wmma::load_matrix_sync(bH, &sBH[(warpN*32 + nt*16)*40 + ks*16], 40);
                wmma::load_matrix_sync(bL, &sBL[(warpN*32 + nt*16)*40 + ks*16], 40);
#pragma unroll
                for (int mt = 0; mt < 2; ++mt) {
                    wmma::mma_sync(acc[mt][nt], aH[mt], bH, acc[mt][nt]);
                    wmma::mma_sync(acc[mt][nt], aH[mt], bL, acc[mt][nt]);
                    wmma::mma_sync(acc[mt][nt], aL[mt], bH, acc[mt][nt]);
                }
            }
        }
        __syncthreads();
    }

#pragma unroll
    for (int mt = 0; mt < 2; ++mt)
#pragma unroll
        for (int nt = 0; nt < 2; ++nt) {
            float* dst = out + (size_t)(mb + warpM*32 + mt*16) * DD + nb + warpN*32 + nt*16;
            wmma::store_matrix_sync(dst, acc[mt][nt], DD, wmma::mem_row_major);
        }
}

// =================================================================================
extern "C" void kernel_launch(void* const* d_in, const int* in_sizes, int n_in,
                              void* d_out, int out_size)
{
    const float* inp    = (const float*)d_in[0];
    const float* W_logA = (const float*)d_in[1];
    const float* b_logA = (const float*)d_in[2];
    const float* W_XBC  = (const float*)d_in[3];
    const float* b_XBC  = (const float*)d_in[4];
    const float* W_gate = (const float*)d_in[5];
    const float* b_gate = (const float*)d_in[6];
    const float* W_out  = (const float*)d_in[7];
    const float* b_out  = (const float*)d_in[8];
    float* out = (float*)d_out;

    cvt_all<<<3328, 256>>>(inp, W_XBC, W_gate, W_out);

    cudaFuncSetAttribute(proj_mma, cudaFuncAttributeMaxDynamicSharedMemorySize, PM_SMEM);
    proj_mma<<<dim3(16, 4, 16), 256, PM_SMEM>>>(b_XBC, b_gate);

    scan_kernel<<<32, 256>>>(inp, W_logA, b_logA);

    state_kernel<<<dim3(NCH-1, BHN), 256>>>();
    scan_state<<<dim3(BHN, 8), 256>>>();

    cudaFuncSetAttribute(attn_chunk, cudaFuncAttributeMaxDynamicSharedMemorySize, AC_SMEM);
    attn_chunk<<<dim3(NCH, BHN), 256, AC_SMEM>>>();

    cudaFuncSetAttribute(out_gemm_wmma, cudaFuncAttributeMaxDynamicSharedMemorySize, OG_SMEM);
    out_gemm_wmma<<<dim3(16, 16), 256, OG_SMEM>>>(b_out, out);
}

// round 17
// speedup vs baseline: 1.9821x; 1.0005x over previous
#include <cuda_runtime.h>
#include <cuda_bf16.h>
#include <mma.h>
#include <math.h>
#include <cstdint>

using namespace nvcuda;

#define BB 2
#define TT 1024
#define DD 1024
#define HH 16
#define CH 64
#define BHN (BB*HH)
#define NCH 16

// ---------------- device scratch ----------------
__device__ __align__(128) float g_cum [BHN*TT];
__device__ __align__(128) float g_gate[BHN*TT*CH];

// hi/lo splits of inputs and packed projection weights
__device__ __align__(128) __nv_bfloat16 g_Ih [BB*TT*DD];
__device__ __align__(128) __nv_bfloat16 g_Il [BB*TT*DD];
__device__ __align__(128) __nv_bfloat16 g_Wph[HH*256*CH];
__device__ __align__(128) __nv_bfloat16 g_Wpl[HH*256*CH];

// bf16 hi/lo activations
__device__ __align__(128) __nv_bfloat16 g_Xh[BHN*TT*CH];
__device__ __align__(128) __nv_bfloat16 g_Xl[BHN*TT*CH];
__device__ __align__(128) __nv_bfloat16 g_Bh[BHN*TT*CH];
__device__ __align__(128) __nv_bfloat16 g_Bl[BHN*TT*CH];
__device__ __align__(128) __nv_bfloat16 g_Chh[BHN*TT*CH];
__device__ __align__(128) __nv_bfloat16 g_Cll[BHN*TT*CH];

// chunked-scan intermediates
__device__ __align__(128) float         g_P  [BHN*NCH*64*64];
__device__ __align__(128) __nv_bfloat16 g_Sth[BHN*NCH*64*64];
__device__ __align__(128) __nv_bfloat16 g_Stl[BHN*NCH*64*64];

// output GEMM operands
__device__ __align__(128) __nv_bfloat16 g_YgH[BB*TT*DD];
__device__ __align__(128) __nv_bfloat16 g_YgL[BB*TT*DD];
__device__ __align__(128) __nv_bfloat16 g_WH [DD*DD];
__device__ __align__(128) __nv_bfloat16 g_WL [DD*DD];

// ---------------- helpers ----------------
__device__ __forceinline__ uint32_t smem_u32(const void* p) {
    uint32_t a;
    asm("{ .reg .u64 t; cvta.to.shared.u64 t, %1; cvt.u32.u64 %0, t; }" : "=r"(a) : "l"(p));
    return a;
}
__device__ __forceinline__ void cp16(uint32_t dst, const void* src) {
    asm volatile("cp.async.cg.shared.global [%0], [%1], 16;" :: "r"(dst), "l"(src) : "memory");
}
#define CP_COMMIT() asm volatile("cp.async.commit_group;" ::: "memory")
#define CP_WAIT(n)  asm volatile("cp.async.wait_group %0;" :: "n"(n) : "memory")

// =================================================================================
// Kernel 0: all fp32 -> bf16 hi/lo conversions (unchanged from R16)
// =================================================================================
__global__ __launch_bounds__(256) void cvt_all(
    const float* __restrict__ inp,  const float* __restrict__ W_XBC,
    const float* __restrict__ W_gate, const float* __restrict__ W_out)
{
    const int i = blockIdx.x * 256 + threadIdx.x;
    float4 v;
    __nv_bfloat16 *dh, *dl;
    int base;
    if (i < 524288) {
        v = ((const float4*)inp)[i];
        dh = g_Ih; dl = g_Il; base = i;
    } else if (i < 524288 + 65536) {
        const int j = i - 524288;
        const int e = j * 4;
        const int hh = e >> 14;
        const int rem = e & 16383;
        const int o = rem >> 6, c = rem & 63;
        const float* s = (o < 192) ? &W_XBC[((size_t)hh*192 + o)*CH + c]
                                   : &W_gate[((size_t)hh*CH + (o-192))*CH + c];
        v = *(const float4*)s;
        dh = g_Wph; dl = g_Wpl; base = j;
    } else {
        base = i - 524288 - 65536;
        v = ((const float4*)W_out)[base];
        dh = g_WH; dl = g_WL;
    }
    float x[4] = {v.x, v.y, v.z, v.w};
    __nv_bfloat16 h[4], l[4];
#pragma unroll
    for (int k = 0; k < 4; ++k) {
        h[k] = __float2bfloat16_rn(x[k]);
        l[k] = __float2bfloat16_rn(x[k] - __bfloat162float(h[k]));
    }
    ((__nv_bfloat162*)dh)[base*2+0] = __halves2bfloat162(h[0], h[1]);
    ((__nv_bfloat162*)dh)[base*2+1] = __halves2bfloat162(h[2], h[3]);
    ((__nv_bfloat162*)dl)[base*2+0] = __halves2bfloat162(l[0], l[1]);
    ((__nv_bfloat162*)dl)[base*2+1] = __halves2bfloat162(l[2], l[3]);
}

// =================================================================================
// Kernel 1: proj via wmma bf16x3 (unchanged from R16)
// =================================================================================
#define PM_XT   18432
#define PM_WT   9216
#define PM_SMEM (2*PM_XT + 2*PM_WT)

__global__ __launch_bounds__(256) void proj_mma(
    const float* __restrict__ b_XBC, const float* __restrict__ b_gate)
{
    extern __shared__ __align__(128) char sm[];
    const uint32_t sbase = smem_u32(sm);
    __nv_bfloat16* Xh_s = (__nv_bfloat16*)sm;
    __nv_bfloat16* Xl_s = (__nv_bfloat16*)(sm + PM_XT);
    __nv_bfloat16* Wh_s = (__nv_bfloat16*)(sm + 2*PM_XT);
    __nv_bfloat16* Wl_s = (__nv_bfloat16*)(sm + 2*PM_XT + PM_WT);
    float* S32 = (float*)sm;

    const int mb  = blockIdx.x * 128;
    const int seg = blockIdx.y;
    const int h   = blockIdx.z;
    const int tid = threadIdx.x;
    const int wid = tid >> 5, warpM = wid & 3, warpN = wid >> 2;

#pragma unroll
    for (int s = 0; s < 8; ++s) {
        int l = tid + s*256;
        int tile = l >> 10, ww = l & 1023, r = ww >> 3, q = ww & 7;
        const __nv_bfloat16* g = (tile ? g_Il : g_Ih) + (size_t)(mb + r)*DD + h*CH + q*8;
        cp16(sbase + (uint32_t)(tile*PM_XT + r*144 + q*16), g);
    }
#pragma unroll
    for (int s = 0; s < 4; ++s) {
        int l = tid + s*256;
        int tile = l >> 9, ww = l & 511, r = ww >> 3, q = ww & 7;
        const __nv_bfloat16* g = (tile ? g_Wpl : g_Wph) + ((size_t)h*256 + seg*64 + r)*CH + q*8;
        cp16(sbase + (uint32_t)(2*PM_XT + tile*PM_WT + r*144 + q*16), g);
    }
    CP_COMMIT();
    CP_WAIT(0);
    __syncthreads();

    wmma::fragment<wmma::accumulator,16,16,16,float> acc[2][2];
#pragma unroll
    for (int mt = 0; mt < 2; ++mt)
#pragma unroll
        for (int nt = 0; nt < 2; ++nt) wmma::fill_fragment(acc[mt][nt], 0.f);

#pragma unroll
    for (int kk = 0; kk < 4; ++kk) {
        wmma::fragment<wmma::matrix_a,16,16,16,__nv_bfloat16,wmma::row_major> aH[2], aL[2];
#pragma unroll
        for (int mt = 0; mt < 2; ++mt) {
            wmma::load_matrix_sync(aH[mt], &Xh_s[(warpM*32 + mt*16)*72 + kk*16], 72);
            wmma::load_matrix_sync(aL[mt], &Xl_s[(warpM*32 + mt*16)*72 + kk*16], 72);
        }
#pragma unroll
        for (int nt = 0; nt < 2; ++nt) {
            wmma::fragment<wmma::matrix_b,16,16,16,__nv_bfloat16,wmma::col_major> bH, bL;
            wmma::load_matrix_sync(bH, &Wh_s[(warpN*32 + nt*16)*72 + kk*16], 72);
            wmma::load_matrix_sync(bL, &Wl_s[(warpN*32 + nt*16)*72 + kk*16], 72);
#pragma unroll
            for (int mt = 0; mt < 2; ++mt) {
                wmma::mma_sync(acc[mt][nt], aH[mt], bH, acc[mt][nt]);
                wmma::mma_sync(acc[mt][nt], aH[mt], bL, acc[mt][nt]);
                wmma::mma_sync(acc[mt][nt], aL[mt], bH, acc[mt][nt]);
            }
        }
    }
    __syncthreads();

#pragma unroll
    for (int mt = 0; mt < 2; ++mt)
#pragma unroll
        for (int nt = 0; nt < 2; ++nt)
            wmma::store_matrix_sync(&S32[(warpM*32 + mt*16)*68 + warpN*32 + nt*16],
                                    acc[mt][nt], 68, wmma::mem_row_major);
    __syncthreads();

    const int row = tid >> 1;
    const int cb  = (tid & 1) * 32;
    const int m   = mb + row;
    const int b_  = m >> 10;
    const int t   = m & (TT-1);
    const int bh  = b_*HH + h;
    const size_t o0 = ((size_t)bh*TT + t)*CH;

    if (seg < 3) {
        const float* bias = b_XBC + h*192 + seg*64;
        __nv_bfloat16 *dh, *dl;
        if (seg == 0)      { dh = g_Xh;  dl = g_Xl;  }
        else if (seg == 1) { dh = g_Bh;  dl = g_Bl;  }
        else               { dh = g_Chh; dl = g_Cll; }
#pragma unroll
        for (int i = 0; i < 32; i += 2) {
            const int c0 = cb + i;
            float z0 = S32[row*68 + c0]     + bias[c0];
            float z1 = S32[row*68 + c0 + 1] + bias[c0 + 1];
            float s0 = z0 / (1.f + __expf(-z0));
            float s1 = z1 / (1.f + __expf(-z1));
            __nv_bfloat16 h0 = __float2bfloat16_rn(s0);
            __nv_bfloat16 h1 = __float2bfloat16_rn(s1);
            *(__nv_bfloat162*)(dh + o0 + c0) = __halves2bfloat162(h0, h1);
            *(__nv_bfloat162*)(dl + o0 + c0) = __halves2bfloat162(
                __float2bfloat16_rn(s0 - __bfloat162float(h0)),
                __float2bfloat16_rn(s1 - __bfloat162float(h1)));
        }
    } else {
        const float* bias = b_gate + h*CH;
#pragma unroll
        for (int i = 0; i < 32; i += 4) {
            const int c0 = cb + i;
            float4 v;
            v.x = S32[row*68 + c0 + 0] + bias[c0 + 0];
            v.y = S32[row*68 + c0 + 1] + bias[c0 + 1];
            v.z = S32[row*68 + c0 + 2] + bias[c0 + 2];
            v.w = S32[row*68 + c0 + 3] + bias[c0 + 3];
            *(float4*)&g_gate[o0 + c0] = v;
        }
    }
}

// =================================================================================
// Kernel 2: fused logA GEMV + inclusive cumsum (unchanged)
// =================================================================================
__global__ __launch_bounds__(256) void scan_kernel(
    const float* __restrict__ inp,
    const float* __restrict__ W_logA, const float* __restrict__ b_logA)
{
    __shared__ float s_tot[256];
    __shared__ float w[64];
    const int bh  = blockIdx.x;
    const int b_  = bh >> 4, h = bh & 15;
    const int tid = threadIdx.x;

    if (tid < 64) w[tid] = W_logA[h*CH + tid];
    __syncthreads();
    const float bA = b_logA[h];

    float v[4];
#pragma unroll
    for (int j = 0; j < 4; ++j) {
        const int t = tid*4 + j;
        const float4* row = (const float4*)&inp[((size_t)b_*TT + t)*DD + h*CH];
        float dot = 0.f;
#pragma unroll
        for (int c4 = 0; c4 < 16; ++c4) {
            float4 x = row[c4];
            dot += x.x*w[c4*4+0] + x.y*w[c4*4+1] + x.z*w[c4*4+2] + x.w*w[c4*4+3];
        }
        v[j] = dot + bA;
    }

    float r0 = v[0], r1 = r0+v[1], r2 = r1+v[2], r3 = r2+v[3];
    float total = r3;
    s_tot[tid] = r3;

    for (int off = 1; off < 256; off <<= 1) {
        __syncthreads();
        float add = (tid >= off) ? s_tot[tid - off] : 0.f;
        __syncthreads();
        s_tot[tid] += add;
    }
    __syncthreads();
    float excl = s_tot[tid] - total;

    float* out = g_cum + bh*TT;
    out[tid*4+0] = excl + r0;
    out[tid*4+1] = excl + r1;
    out[tid*4+2] = excl + r2;
    out[tid*4+3] = excl + r3;
}

// =================================================================================
// Kernel 3a: chunk moments P_k = B'^T @ X.
// B' rebuild VECTORIZED: uint4 loads of 8 bf16 from Bh/Bl (2 LDG.128/thread vs
// 32 scalar LDG), re-split, uint4 stores to smem.
// =================================================================================
#define KC_LDS 72
__global__ __launch_bounds__(256) void state_kernel()
{
    __shared__ __nv_bfloat16 Bp_h[64*KC_LDS], Bp_l[64*KC_LDS];
    __shared__ __nv_bfloat16 Xh_s[64*KC_LDS], Xl_s[64*KC_LDS];
    __shared__ float sc[64];

    const int k   = blockIdx.x;
    const int bh  = blockIdx.y;
    const int tid = threadIdx.x;
    const int w = tid >> 5, mrow = w & 3, nh = w >> 2;

    const uint32_t xh_b = smem_u32(Xh_s), xl_b = smem_u32(Xl_s);
#pragma unroll
    for (int s = 0; s < 4; ++s) {
        int l = tid + s*256;
        int tile = l >> 9, ww = l & 511, r = ww >> 3, q = ww & 7;
        const __nv_bfloat16* g = (tile ? g_Xl : g_Xh) + ((size_t)bh*TT + k*64 + r)*CH + q*8;
        cp16((tile ? xl_b : xh_b) + (uint32_t)(r*144 + q*16), g);
    }
    CP_COMMIT();
    if (tid < 64)
        sc[tid] = __expf(g_cum[bh*TT + k*64 + 63] - g_cum[bh*TT + k*64 + tid]);
    __syncthreads();

    // B' rebuild: 512 groups of 8 bf16; thread handles 2 groups via uint4.
#pragma unroll
    for (int s = 0; s < 2; ++s) {
        const int l  = tid + s*256;            // < 512
        const int ii = l >> 3, q = l & 7;
        const size_t go = ((size_t)bh*TT + k*64 + ii)*CH + q*8;
        const uint4 vh = *(const uint4*)(g_Bh + go);
        const uint4 vl = *(const uint4*)(g_Bl + go);
        const float scale = sc[ii];
        const uint32_t uh[4] = {vh.x, vh.y, vh.z, vh.w};
        const uint32_t ul[4] = {vl.x, vl.y, vl.z, vl.w};
        uint32_t oh[4], ol[4];
#pragma unroll
        for (int p = 0; p < 4; ++p) {
            __nv_bfloat162 bh2 = *(const __nv_bfloat162*)&uh[p];
            __nv_bfloat162 bl2 = *(const __nv_bfloat162*)&ul[p];
            float v0 = (__bfloat162float(__low2bfloat16(bh2))  + __bfloat162float(__low2bfloat16(bl2)))  * scale;
            float v1 = (__bfloat162float(__high2bfloat16(bh2)) + __bfloat162float(__high2bfloat16(bl2))) * scale;
            __nv_bfloat16 h0 = __float2bfloat16_rn(v0);
            __nv_bfloat16 h1 = __float2bfloat16_rn(v1);
            __nv_bfloat162 hh2 = __halves2bfloat162(h0, h1);
            __nv_bfloat162 ll2 = __halves2bfloat162(
                __float2bfloat16_rn(v0 - __bfloat162float(h0)),
                __float2bfloat16_rn(v1 - __bfloat162float(h1)));
            oh[p] = *(const uint32_t*)&hh2;
            ol[p] = *(const uint32_t*)&ll2;
        }
        *(uint4*)&Bp_h[ii*KC_LDS + q*8] = make_uint4(oh[0], oh[1], oh[2], oh[3]);
        *(uint4*)&Bp_l[ii*KC_LDS + q*8] = make_uint4(ol[0], ol[1], ol[2], ol[3]);
    }
    CP_WAIT(0);
    __syncthreads();

    wmma::fragment<wmma::accumulator,16,16,16,float> pacc[2];
#pragma unroll
    for (int t2 = 0; t2 < 2; ++t2) wmma::fill_fragment(pacc[t2], 0.f);
#pragma unroll
    for (int kk = 0; kk < 4; ++kk) {
        wmma::fragment<wmma::matrix_a,16,16,16,__nv_bfloat16,wmma::col_major> aH, aL;
        wmma::load_matrix_sync(aH, &Bp_h[(kk*16)*KC_LDS + mrow*16], KC_LDS);
        wmma::load_matrix_sync(aL, &Bp_l[(kk*16)*KC_LDS + mrow*16], KC_LDS);
#pragma unroll
        for (int t2 = 0; t2 < 2; ++t2) {
            const int nt = nh*2 + t2;
            wmma::fragment<wmma::matrix_b,16,16,16,__nv_bfloat16,wmma::row_major> bH, bL;
            wmma::load_matrix_sync(bH, &Xh_s[(kk*16)*KC_LDS + nt*16], KC_LDS);
            wmma::load_matrix_sync(bL, &Xl_s[(kk*16)*KC_LDS + nt*16], KC_LDS);
            wmma::mma_sync(pacc[t2], aH, bH, pacc[t2]);
            wmma::mma_sync(pacc[t2], aH, bL, pacc[t2]);
            wmma::mma_sync(pacc[t2], aL, bH, pacc[t2]);
        }
    }
#pragma unroll
    for (int t2 = 0; t2 < 2; ++t2) {
        float* dst = g_P + ((size_t)bh*NCH + k)*4096 + (mrow*16)*64 + (nh*2+t2)*16;
        wmma::store_matrix_sync(dst, pacc[t2], 64, wmma::mem_row_major);
    }
}

// =================================================================================
// Kernel 3b: state scan (prefetched, unchanged)
// =================================================================================
__global__ __launch_bounds__(256) void scan_state()
{
    __shared__ float d[16];
    const int bh  = blockIdx.x;
    const int eb  = blockIdx.y * 512;
    const int tid = threadIdx.x;
    const int base = eb + tid*2;

    if (tid < 15) {
        float Ek = g_cum[bh*TT + tid*64 + 63];
        float Ep = (tid > 0) ? g_cum[bh*TT + tid*64 - 1] : 0.f;
        d[tid] = __expf(Ek - Ep);
    }

    float2 P[15];
#pragma unroll
    for (int k = 0; k < 15; ++k)
        P[k] = *(const float2*)&g_P[((size_t)bh*NCH + k)*4096 + base];
    __syncthreads();

    float2 S = make_float2(0.f, 0.f);
#pragma unroll
    for (int k = 0; k < 16; ++k) {
        size_t so = ((size_t)bh*NCH + k)*4096 + base;
        __nv_bfloat16 hx = __float2bfloat16_rn(S.x);
        __nv_bfloat16 hy = __float2bfloat16_rn(S.y);
        *(__nv_bfloat162*)(g_Sth + so) = __halves2bfloat162(hx, hy);
        *(__nv_bfloat162*)(g_Stl + so) = __halves2bfloat162(
            __float2bfloat16_rn(S.x - __bfloat162float(hx)),
            __float2bfloat16_rn(S.y - __bfloat162float(hy)));
        if (k < 15) {
            S.x = d[k]*S.x + P[k].x;
            S.y = d[k]*S.y + P[k].y;
        }
    }
}

// =================================================================================
// Kernel 3c: per-chunk output (unchanged)
// =================================================================================
#define AC_TILE (64*KC_LDS*2)
#define AC_S32A (8*AC_TILE)
#define AC_S32B (AC_S32A + 64*68*4)
#define AC_SCI  (AC_S32B + 64*68*4)
#define AC_SMEM (AC_SCI + 2*64*4)

__global__ __launch_bounds__(256) void attn_chunk()
{
    extern __shared__ __align__(128) char sm[];
    const uint32_t sbase = smem_u32(sm);
    __nv_bfloat16* Ch  = (__nv_bfloat16*)(sm);
    __nv_bfloat16* Cl  = (__nv_bfloat16*)(sm + 1*AC_TILE);
    __nv_bfloat16* Bh  = (__nv_bfloat16*)(sm + 2*AC_TILE);
    __nv_bfloat16* Bl  = (__nv_bfloat16*)(sm + 3*AC_TILE);
    __nv_bfloat16* Xh  = (__nv_bfloat16*)(sm + 4*AC_TILE);
    __nv_bfloat16* Xl  = (__nv_bfloat16*)(sm + 5*AC_TILE);
    __nv_bfloat16* Sth = (__nv_bfloat16*)(sm + 6*AC_TILE);
    __nv_bfloat16* Stl = (__nv_bfloat16*)(sm + 7*AC_TILE);
    float* S32a = (float*)(sm + AC_S32A);
    float* S32b = (float*)(sm + AC_S32B);
    float* sCi  = (float*)(sm + AC_SCI);
    float* sCj  = sCi + 64;

    const int k   = blockIdx.x;
    const int bh  = blockIdx.y;
    const int tid = threadIdx.x;
    const int w = tid >> 5, mrow = w & 3, nh = w >> 2;

    {
        const __nv_bfloat16* act[6] = {g_Chh, g_Cll, g_Bh, g_Bl, g_Xh, g_Xl};
#pragma unroll
        for (int s = 0; s < 12; ++s) {
            int l = tid + s*256;
            int tile = l >> 9, ww = l & 511, r = ww >> 3, q = ww & 7;
            const __nv_bfloat16* g = act[tile] + ((size_t)bh*TT + k*64 + r)*CH + q*8;
            cp16(sbase + (uint32_t)(tile*AC_TILE + r*144 + q*16), g);
        }
#pragma unroll
        for (int s = 0; s < 4; ++s) {
            int l = tid + s*256;
            int tile = l >> 9, ww = l & 511, r = ww >> 3, q = ww & 7;
            const __nv_bfloat16* g = (tile ? g_Stl : g_Sth) + ((size_t)bh*NCH + k)*4096 + r*64 + q*8;
            cp16(sbase + (uint32_t)((6+tile)*AC_TILE + r*144 + q*16), g);
        }
        CP_COMMIT();
    }
    {
        const float bk = (k > 0) ? g_cum[bh*TT + k*64 - 1] : 0.f;
        if (tid < 64)  sCi[tid] = __expf(g_cum[bh*TT + k*64 + tid] - bk);
        else if (tid < 128) sCj[tid-64] = __expf(bk - g_cum[bh*TT + k*64 + (tid-64)]);
    }
    CP_WAIT(0);
    __syncthreads();

    wmma::fragment<wmma::accumulator,16,16,16,float> sacc[2];
#pragma unroll
    for (int t2 = 0; t2 < 2; ++t2) wmma::fill_fragment(sacc[t2], 0.f);
#pragma unroll
    for (int kk = 0; kk < 4; ++kk) {
        wmma::fragment<wmma::matrix_a,16,16,16,__nv_bfloat16,wmma::row_major> aH, aL;
        wmma::load_matrix_sync(aH, &Ch[(mrow*16)*KC_LDS + kk*16], KC_LDS);
        wmma::load_matrix_sync(aL, &Cl[(mrow*16)*KC_LDS + kk*16], KC_LDS);
#pragma unroll
        for (int t2 = 0; t2 < 2; ++t2) {
            const int nt = nh*2 + t2;
            wmma::fragment<wmma::matrix_b,16,16,16,__nv_bfloat16,wmma::col_major> bH, bL;
            wmma::load_matrix_sync(bH, &Bh[(nt*16)*KC_LDS + kk*16], KC_LDS);
            wmma::load_matrix_sync(bL, &Bl[(nt*16)*KC_LDS + kk*16], KC_LDS);
            wmma::mma_sync(sacc[t2], aH, bH, sacc[t2]);
            wmma::mma_sync(sacc[t2], aH, bL, sacc[t2]);
            wmma::mma_sync(sacc[t2], aL, bH, sacc[t2]);
        }
    }
#pragma unroll
    for (int t2 = 0; t2 < 2; ++t2)
        wmma::store_matrix_sync(&S32a[(mrow*16)*68 + (nh*2+t2)*16], sacc[t2], 68,
                                wmma::mem_row_major);
    __syncthreads();

#pragma unroll
    for (int q = 0; q < 16; ++q) {
        int idx = (tid & 31) + q*32;
        int ii = mrow*16 + (idx >> 5);
        int jj = nh*32 + (idx & 31);
        float v = S32a[ii*68 + jj] * sCi[ii] * sCj[jj];
        if (jj > ii) v = 0.f;
        __nv_bfloat16 h = __float2bfloat16_rn(v);
        Bh[ii*KC_LDS + jj] = h;
        Bl[ii*KC_LDS + jj] = __float2bfloat16_rn(v - __bfloat162float(h));
    }
    __syncthreads();

    wmma::fragment<wmma::accumulator,16,16,16,float> yacc[2], zacc[2];
#pragma unroll
    for (int t2 = 0; t2 < 2; ++t2) { wmma::fill_fragment(yacc[t2], 0.f); wmma::fill_fragment(zacc[t2], 0.f); }
#pragma unroll
    for (int kk = 0; kk < 4; ++kk) {
        wmma::fragment<wmma::matrix_a,16,16,16,__nv_bfloat16,wmma::row_major> aH, aL, cH, cL;
        wmma::load_matrix_sync(aH, &Bh[(mrow*16)*KC_LDS + kk*16], KC_LDS);
        wmma::load_matrix_sync(aL, &Bl[(mrow*16)*KC_LDS + kk*16], KC_LDS);
        wmma::load_matrix_sync(cH, &Ch[(mrow*16)*KC_LDS + kk*16], KC_LDS);
        wmma::load_matrix_sync(cL, &Cl[(mrow*16)*KC_LDS + kk*16], KC_LDS);
#pragma unroll
        for (int t2 = 0; t2 < 2; ++t2) {
            const int ct = nh*2 + t2;
            wmma::fragment<wmma::matrix_b,16,16,16,__nv_bfloat16,wmma::row_major> bH, bL, sH, sL;
            wmma::load_matrix_sync(bH, &Xh[(kk*16)*KC_LDS + ct*16], KC_LDS);
            wmma::load_matrix_sync(bL, &Xl[(kk*16)*KC_LDS + ct*16], KC_LDS);
            wmma::mma_sync(yacc[t2], aH, bH, yacc[t2]);
            wmma::mma_sync(yacc[t2], aH, bL, yacc[t2]);
            wmma::mma_sync(yacc[t2], aL, bH, yacc[t2]);
            wmma::load_matrix_sync(sH, &Sth[(kk*16)*KC_LDS + ct*16], KC_LDS);
            wmma::load_matrix_sync(sL, &Stl[(kk*16)*KC_LDS + ct*16], KC_LDS);
            wmma::mma_sync(zacc[t2], cH, sH, zacc[t2]);
            wmma::mma_sync(zacc[t2], cH, sL, zacc[t2]);
            wmma::mma_sync(zacc[t2], cL, sH, zacc[t2]);
        }
    }
#pragma unroll
    for (int t2 = 0; t2 < 2; ++t2) {
        wmma::store_matrix_sync(&S32a[(mrow*16)*68 + (nh*2+t2)*16], yacc[t2], 68, wmma::mem_row_major);
        wmma::store_matrix_sync(&S32b[(mrow*16)*68 + (nh*2+t2)*16], zacc[t2], 68, wmma::mem_row_major);
    }
    __syncwarp();

    const int b_ = bh >> 4, h = bh & 15;
#pragma unroll
    for (int q = 0; q < 16; ++q) {
        int idx = (tid & 31) + q*32;
        int ii = mrow*16 + (idx >> 5);
        int cc = nh*32 + (idx & 31);
        float y = S32a[ii*68 + cc] + sCi[ii] * S32b[ii*68 + cc];
        float v = y * g_gate[((size_t)bh*TT + k*64 + ii)*CH + cc];
        size_t o = ((size_t)b_*TT + k*64 + ii)*DD + h*CH + cc;
        __nv_bfloat16 hh = __float2bfloat16_rn(v);
        g_YgH[o] = hh;
        g_YgL[o] = __float2bfloat16_rn(v - __bfloat162float(hh));
    }
}

// =================================================================================
// out_gemm_wmma: CTA tile 128(M) x 64(N), grid 16x16, 256 threads (unchanged)
// =================================================================================
#define NCHUNK   32
#define TA_B     10240
#define TB_B     5120
#define STAGE_B  (2*TA_B + 2*TB_B)
#define BIAS_OFF (2*STAGE_B)
#define OG_SMEM  (BIAS_OFF + 16*64*4)

__global__ __launch_bounds__(256) void out_gemm_wmma(
    const float* __restrict__ b_out, float* __restrict__ out)
{
    extern __shared__ __align__(128) char smem[];
    const uint32_t sbase = smem_u32(smem);
    __nv_bfloat16* s_bf = (__nv_bfloat16*)smem;
    float* bias_s = (float*)(smem + BIAS_OFF);

    const int tid  = threadIdx.x;
    const int wid  = tid >> 5;
    const int warpM = wid & 3;
    const int warpN = wid >> 2;
    const int mb = blockIdx.x * 128;
    const int nb = blockIdx.y * 64;

    auto issue_stage = [&](int chunk, int p) {
        const int kc = chunk * 32;
        const uint32_t sb = sbase + (uint32_t)p * STAGE_B;
#pragma unroll
        for (int s = 0; s < 6; ++s) {
            const int l = tid + s * 256;
            const __nv_bfloat16* src;
            uint32_t dst;
            if (l < 512)        { int r = l >> 2, q = l & 3;
                src = g_YgH + (size_t)(mb + r) * DD + kc + q * 8;
                dst = sb + r * 80 + q * 16; }
            else if (l < 1024)  { int r = (l - 512) >> 2, q = l & 3;
                src = g_YgL + (size_t)(mb + r) * DD + kc + q * 8;
                dst = sb + TA_B + r * 80 + q * 16; }
            else if (l < 1280)  { int r = (l - 1024) >> 2, q = l & 3;
                src = g_WH + (size_t)(nb + r) * DD + kc + q * 8;
                dst = sb + 2*TA_B + r * 80 + q * 16; }
            else                { int r = (l - 1280) >> 2, q = l & 3;
                src = g_WL + (size_t)(nb + r) * DD + kc + q * 8;
                dst = sb + 2*TA_B + TB_B + r * 80 + q * 16; }
            cp16(dst, src);
        }
        CP_COMMIT();
    };

    issue_stage(0, 0);

    for (int i = tid; i < 16*64; i += 256) bias_s[i] = b_out[nb + (i & 63)];
    __syncthreads();

    wmma::fragment<wmma::accumulator, 16, 16, 16, float> acc[2][2];
#pragma unroll
    for (int mt = 0; mt < 2; ++mt)
#pragma unroll
        for (int nt = 0; nt < 2; ++nt)
            wmma::load_matrix_sync(acc[mt][nt], &bias_s[warpN*32 + nt*16], 64,
                                   wmma::mem_row_major);

    for (int c = 0; c < NCHUNK; ++c) {
        const int p = c & 1;
        if (c + 1 < NCHUNK) { issue_stage(c + 1, p ^ 1); CP_WAIT(1); }
        else                { CP_WAIT(0); }
        __syncthreads();

        __nv_bfloat16* sAH = s_bf + (size_t)p * (STAGE_B/2);
        __nv_bfloat16* sAL = sAH + TA_B/2;
        __nv_bfloat16* sBH = sAH + TA_B;
        __nv_bfloat16* sBL = sAH + TA_B + TB_B/2;

#pragma unroll
        for (int ks = 0; ks < 2; ++ks) {
            wmma::fragment<wmma::matrix_a, 16, 16, 16, __nv_bfloat16, wmma::row_major> aH[2], aL[2];
#pragma unroll
            for (int mt = 0; mt < 2; ++mt) {
                wmma::load_matrix_sync(aH[mt], &sAH[(warpM*32 + mt*16)*40 + ks*16], 40);
                wmma::load_matrix_sync(aL[mt], &sAL[(warpM*32 + mt*16)*40 + ks*16], 40);
            }
#pragma unroll
            for (int nt = 0; nt < 2; ++nt) {
                wmma::fragment<wmma::matrix_b, 16, 16, 16, __nv_bfloat16, wmma::col_major> bH, bL;
                wmma::load_matrix_sync(bH, &sBH[(warpN*32 + nt*16)*40 + ks*16], 40);
                wmma::load_matrix_sync(bL, &sBL[(warpN*32 + nt*16)*40 + ks*16], 40);
#pragma unroll
                for (int mt = 0; mt < 2; ++mt) {
                    wmma::mma_sync(acc[mt][nt], aH[mt], bH, acc[mt][nt]);
                    wmma::mma_sync(acc[mt][nt], aH[mt], bL, acc[mt][nt]);
                    wmma::mma_sync(acc[mt][nt], aL[mt], bH, acc[mt][nt]);
                }
            }
        }
        __syncthreads();
    }

#pragma unroll
    for (int mt = 0; mt < 2; ++mt)
#pragma unroll
        for (int nt = 0; nt < 2; ++nt) {
            float* dst = out + (size_t)(mb + warpM*32 + mt*16) * DD + nb + warpN*32 + nt*16;
            wmma::store_matrix_sync(dst, acc[mt][nt], DD, wmma::mem_row_major);
        }
}

// =================================================================================
extern "C" void kernel_launch(void* const* d_in, const int* in_sizes, int n_in,
                              void* d_out, int out_size)
{
    const float* inp    = (const float*)d_in[0];
    const float* W_logA = (const float*)d_in[1];
    const float* b_logA = (const float*)d_in[2];
    const float* W_XBC  = (const float*)d_in[3];
    const float* b_XBC  = (const float*)d_in[4];
    const float* W_gate = (const float*)d_in[5];
    const float* b_gate = (const float*)d_in[6];
    const float* W_out  = (const float*)d_in[7];
    const float* b_out  = (const float*)d_in[8];
    float* out = (float*)d_out;

    cvt_all<<<3328, 256>>>(inp, W_XBC, W_gate, W_out);

    cudaFuncSetAttribute(proj_mma, cudaFuncAttributeMaxDynamicSharedMemorySize, PM_SMEM);
    proj_mma<<<dim3(16, 4, 16), 256, PM_SMEM>>>(b_XBC, b_gate);

    scan_kernel<<<32, 256>>>(inp, W_logA, b_logA);

    state_kernel<<<dim3(NCH-1, BHN), 256>>>();
    scan_state<<<dim3(BHN, 8), 256>>>();

    cudaFuncSetAttribute(attn_chunk, cudaFuncAttributeMaxDynamicSharedMemorySize, AC_SMEM);
    attn_chunk<<<dim3(NCH, BHN), 256, AC_SMEM>>>();

    cudaFuncSetAttribute(out_gemm_wmma, cudaFuncAttributeMaxDynamicSharedMemorySize, OG_SMEM);
    out_gemm_wmma<<<dim3(16, 16), 256, OG_SMEM>>>(b_out, out);
}